// round 1
// baseline (speedup 1.0000x reference)
#include <cuda_runtime.h>
#include <cuda_bf16.h>

#define D 256
#define NNODES 32768
#define NREL 10
#define NBASES 4
#define NEDGES 524288
#define NCOLS 1280   // NBASES*D (basis projections) + D (root projection)

// ---------------- scratch (static device allocations; no cudaMalloc) ----------------
__device__ float g_z[(size_t)NNODES * NCOLS];     // 160 MB: per-node [xb(1024) | root(256)]
__device__ float g_h1[(size_t)NNODES * D];        // 32 MB: hidden activations
__device__ float g_Bcat[D * NCOLS];               // fused weight matrix per layer
__device__ int   g_cnt[NREL * NNODES];            // per-(rel,dst) edge counts
__device__ int   g_deg[NNODES];                   // per-dst degree
__device__ int   g_rowptr[NNODES + 1];            // CSR row pointers (by dst)
__device__ int   g_cursor[NNODES];                // scatter cursors
__device__ int   g_perm[NEDGES];                  // CSR edge permutation

// ---------------- zero the histogram buffers ----------------
__global__ void zero_counts_kernel() {
    int i = blockIdx.x * blockDim.x + threadIdx.x;
    int total = NNODES + NREL * NNODES;
    for (; i < total; i += gridDim.x * blockDim.x) {
        if (i < NNODES) g_deg[i] = 0;
        else            g_cnt[i - NNODES] = 0;
    }
}

// ---------------- histogram: degree per dst + count per (rel,dst) ----------------
__global__ void hist_kernel(const int* __restrict__ dst, const int* __restrict__ rel) {
    int e = blockIdx.x * blockDim.x + threadIdx.x;
    if (e >= NEDGES) return;
    int d = dst[e];
    int r = rel[e];
    atomicAdd(&g_deg[d], 1);
    atomicAdd(&g_cnt[r * NNODES + d], 1);
}

// ---------------- exclusive scan of g_deg -> g_rowptr / g_cursor (single block) ----
__global__ void scan_kernel() {
    __shared__ int sums[1024];
    const int t = threadIdx.x;           // 1024 threads, 32 elements each
    const int base = t * 32;
    int local[32];
    int s = 0;
#pragma unroll
    for (int i = 0; i < 32; ++i) { local[i] = s; s += g_deg[base + i]; }
    sums[t] = s;
    __syncthreads();
    // Hillis-Steele inclusive scan over 1024 partials
    for (int off = 1; off < 1024; off <<= 1) {
        int v = 0;
        if (t >= off) v = sums[t - off];
        __syncthreads();
        if (t >= off) sums[t] += v;
        __syncthreads();
    }
    const int chunk_off = (t == 0) ? 0 : sums[t - 1];
#pragma unroll
    for (int i = 0; i < 32; ++i) {
        int v = chunk_off + local[i];
        g_rowptr[base + i] = v;
        g_cursor[base + i] = v;
    }
    if (t == 1023) g_rowptr[NNODES] = sums[1023];
}

// ---------------- scatter edge ids into CSR order ----------------
__global__ void scatter_kernel(const int* __restrict__ dst) {
    int e = blockIdx.x * blockDim.x + threadIdx.x;
    if (e >= NEDGES) return;
    int d = dst[e];
    int p = atomicAdd(&g_cursor[d], 1);
    g_perm[p] = e;
}

// ---------------- build fused weight matrix [D, NCOLS] = [basis_flat | root] ------
__global__ void build_bcat_kernel(const float* __restrict__ basis,
                                  const float* __restrict__ root) {
    int idx = blockIdx.x * blockDim.x + threadIdx.x;
    if (idx >= D * NCOLS) return;
    int i = idx / NCOLS;
    int c = idx % NCOLS;
    float v;
    if (c < NBASES * D) {
        int b = c >> 8;          // D == 256
        int o = c & 255;
        v = basis[((size_t)b * D + i) * D + o];   // basis[b, i, o]
    } else {
        v = root[i * D + (c - NBASES * D)];
    }
    g_Bcat[idx] = v;
}

// ---------------- fp32 GEMM: g_z[M, NCOLS] = A[M, D] @ g_Bcat[D, NCOLS] -----------
// 128x128 tile, BK=16, 256 threads, 8x8 per thread.
__global__ __launch_bounds__(256) void sgemm_kernel(const float* __restrict__ Aext,
                                                    int use_ext) {
    const float* __restrict__ A = use_ext ? Aext : g_h1;
    const float* __restrict__ B = g_Bcat;
    float* __restrict__ C = g_z;
    const int K = D;
    const int N = NCOLS;

    __shared__ __align__(16) float As[16][128];
    __shared__ __align__(16) float Bs[16][128];

    const int tid = threadIdx.x;
    const int tx = tid & 15;      // N direction
    const int ty = tid >> 4;      // M direction
    const int bx = blockIdx.x * 128;
    const int by = blockIdx.y * 128;

    float acc[8][8] = {};

    const int a_r = tid >> 2;           // 0..63 (two passes: +0, +64)
    const int a_c = (tid & 3) << 2;     // 0,4,8,12
    const int b_r = tid >> 5;           // 0..7  (two passes: +0, +8)
    const int b_c = (tid & 31) << 2;    // 0..124

    for (int k0 = 0; k0 < K; k0 += 16) {
#pragma unroll
        for (int p = 0; p < 2; ++p) {
            float4 v = *(const float4*)(A + (size_t)(by + a_r + p * 64) * K + k0 + a_c);
            As[a_c + 0][a_r + p * 64] = v.x;
            As[a_c + 1][a_r + p * 64] = v.y;
            As[a_c + 2][a_r + p * 64] = v.z;
            As[a_c + 3][a_r + p * 64] = v.w;
        }
#pragma unroll
        for (int p = 0; p < 2; ++p) {
            *(float4*)(&Bs[b_r + p * 8][b_c]) =
                *(const float4*)(B + (size_t)(k0 + b_r + p * 8) * N + bx + b_c);
        }
        __syncthreads();
#pragma unroll
        for (int k = 0; k < 16; ++k) {
            float4 a0 = *(const float4*)(&As[k][ty * 8]);
            float4 a1 = *(const float4*)(&As[k][ty * 8 + 4]);
            float4 b0 = *(const float4*)(&Bs[k][tx * 8]);
            float4 b1 = *(const float4*)(&Bs[k][tx * 8 + 4]);
            float a[8] = {a0.x, a0.y, a0.z, a0.w, a1.x, a1.y, a1.z, a1.w};
            float b[8] = {b0.x, b0.y, b0.z, b0.w, b1.x, b1.y, b1.z, b1.w};
#pragma unroll
            for (int i = 0; i < 8; ++i)
#pragma unroll
                for (int j = 0; j < 8; ++j)
                    acc[i][j] += a[i] * b[j];
        }
        __syncthreads();
    }
#pragma unroll
    for (int i = 0; i < 8; ++i) {
        float* Cp = C + (size_t)(by + ty * 8 + i) * N + bx + tx * 8;
        *(float4*)(Cp)     = make_float4(acc[i][0], acc[i][1], acc[i][2], acc[i][3]);
        *(float4*)(Cp + 4) = make_float4(acc[i][4], acc[i][5], acc[i][6], acc[i][7]);
    }
}

// ---------------- atomic-free aggregation: one block (64 threads) per dst ---------
// out[dst, :] = sum_{e: dst} (sum_b comp[rel_e,b]/cnt[rel_e,dst] * xb[src_e, b, :])
//               + root_proj[dst, :] + bias[:]   (optional ReLU)
__global__ void aggregate_kernel(const int* __restrict__ src,
                                 const int* __restrict__ rel,
                                 const float* __restrict__ comp,
                                 const float* __restrict__ bias,
                                 float* __restrict__ out_ext,
                                 int layer) {
    const int dst = blockIdx.x;
    const int t = threadIdx.x;   // 64 threads, each handles a float4 (4 cols)
    __shared__ float scomp[NREL * NBASES];
    if (t < NREL * NBASES) scomp[t] = comp[t];
    __syncthreads();

    float4 acc = make_float4(0.f, 0.f, 0.f, 0.f);
    const int beg = g_rowptr[dst];
    const int end = g_rowptr[dst + 1];
    for (int e = beg; e < end; ++e) {
        const int eid = g_perm[e];
        const int s = __ldg(&src[eid]);
        const int r = __ldg(&rel[eid]);
        const float inv = 1.0f / (float)g_cnt[r * NNODES + dst];
        const float w0 = scomp[r * 4 + 0] * inv;
        const float w1 = scomp[r * 4 + 1] * inv;
        const float w2 = scomp[r * 4 + 2] * inv;
        const float w3 = scomp[r * 4 + 3] * inv;
        const float4* xb = (const float4*)(g_z + (size_t)s * NCOLS);
        float4 v0 = __ldg(&xb[t]);
        float4 v1 = __ldg(&xb[64 + t]);
        float4 v2 = __ldg(&xb[128 + t]);
        float4 v3 = __ldg(&xb[192 + t]);
        acc.x += w0 * v0.x + w1 * v1.x + w2 * v2.x + w3 * v3.x;
        acc.y += w0 * v0.y + w1 * v1.y + w2 * v2.y + w3 * v3.y;
        acc.z += w0 * v0.z + w1 * v1.z + w2 * v2.z + w3 * v3.z;
        acc.w += w0 * v0.w + w1 * v1.w + w2 * v2.w + w3 * v3.w;
    }
    const float4 base = __ldg((const float4*)(g_z + (size_t)dst * NCOLS + NBASES * D) + t);
    const float4 bi = __ldg((const float4*)bias + t);
    float4 o;
    o.x = acc.x + base.x + bi.x;
    o.y = acc.y + base.y + bi.y;
    o.z = acc.z + base.z + bi.z;
    o.w = acc.w + base.w + bi.w;
    if (layer == 0) {
        o.x = fmaxf(o.x, 0.f);
        o.y = fmaxf(o.y, 0.f);
        o.z = fmaxf(o.z, 0.f);
        o.w = fmaxf(o.w, 0.f);
        ((float4*)g_h1)[(size_t)dst * 64 + t] = o;
    } else {
        ((float4*)out_ext)[(size_t)dst * 64 + t] = o;
    }
}

// ---------------- launch ----------------
extern "C" void kernel_launch(void* const* d_in, const int* in_sizes, int n_in,
                              void* d_out, int out_size) {
    const float* x      = (const float*)d_in[0];        // [16,2048,256] == [32768,256]
    const int*   edges  = (const int*)d_in[3];          // [2, E]
    const int*   rel    = (const int*)d_in[4];          // [E]
    const float* basis0 = (const float*)d_in[5];
    const float* comp0  = (const float*)d_in[6];
    const float* root0  = (const float*)d_in[7];
    const float* bias0  = (const float*)d_in[8];
    const float* basis1 = (const float*)d_in[9];
    const float* comp1  = (const float*)d_in[10];
    const float* root1  = (const float*)d_in[11];
    const float* bias1  = (const float*)d_in[12];
    float* out = (float*)d_out;

    const int* src = edges;
    const int* dst = edges + NEDGES;

    // CSR + normalization counts (shared by both layers)
    zero_counts_kernel<<<1408, 256>>>();
    hist_kernel<<<(NEDGES + 255) / 256, 256>>>(dst, rel);
    scan_kernel<<<1, 1024>>>();
    scatter_kernel<<<(NEDGES + 255) / 256, 256>>>(dst);

    dim3 gemm_grid(NCOLS / 128, NNODES / 128);

    // Layer 0: x -> h1 (ReLU)
    build_bcat_kernel<<<(D * NCOLS + 255) / 256, 256>>>(basis0, root0);
    sgemm_kernel<<<gemm_grid, 256>>>(x, 1);
    aggregate_kernel<<<NNODES, 64>>>(src, rel, comp0, bias0, nullptr, 0);

    // Layer 1: h1 -> out
    build_bcat_kernel<<<(D * NCOLS + 255) / 256, 256>>>(basis1, root1);
    sgemm_kernel<<<gemm_grid, 256>>>(nullptr, 0);
    aggregate_kernel<<<NNODES, 64>>>(src, rel, comp1, bias1, out, 1);
}

// round 2
// speedup vs baseline: 1.0002x; 1.0002x over previous
#include <cuda_runtime.h>
#include <cuda_bf16.h>

#define D 256
#define NNODES 32768
#define NREL 10
#define NBASES 4
#define NEDGES 524288
#define NCOLS 1280   // NBASES*D (basis projections) + D (root projection)

// ---------------- scratch (static device allocations; no cudaMalloc) ----------------
__device__ float g_z[(size_t)NNODES * NCOLS];     // 160 MB: per-node [xb(1024) | root(256)]
__device__ float g_h1[(size_t)NNODES * D];        // 32 MB: hidden activations
__device__ float g_Bcat[D * NCOLS];               // fused weight matrix per layer
__device__ int   g_cnt[NREL * NNODES];            // per-(rel,dst) edge counts
__device__ int   g_deg[NNODES];                   // per-dst degree
__device__ int   g_rowptr[NNODES + 1];            // CSR row pointers (by dst)
__device__ int   g_cursor[NNODES];                // scatter cursors
__device__ int   g_perm[NEDGES];                  // CSR edge permutation

// ---------------- zero the histogram buffers ----------------
__global__ void zero_counts_kernel() {
    int i = blockIdx.x * blockDim.x + threadIdx.x;
    int total = NNODES + NREL * NNODES;
    for (; i < total; i += gridDim.x * blockDim.x) {
        if (i < NNODES) g_deg[i] = 0;
        else            g_cnt[i - NNODES] = 0;
    }
}

// ---------------- histogram: degree per dst + count per (rel,dst) ----------------
__global__ void hist_kernel(const int* __restrict__ dst, const int* __restrict__ rel) {
    int e = blockIdx.x * blockDim.x + threadIdx.x;
    if (e >= NEDGES) return;
    int d = dst[e];
    int r = rel[e];
    atomicAdd(&g_deg[d], 1);
    atomicAdd(&g_cnt[r * NNODES + d], 1);
}

// ---------------- exclusive scan of g_deg -> g_rowptr / g_cursor (single block) ----
__global__ void scan_kernel() {
    __shared__ int sums[1024];
    const int t = threadIdx.x;           // 1024 threads, 32 elements each
    const int base = t * 32;
    int local[32];
    int s = 0;
#pragma unroll
    for (int i = 0; i < 32; ++i) { local[i] = s; s += g_deg[base + i]; }
    sums[t] = s;
    __syncthreads();
    // Hillis-Steele inclusive scan over 1024 partials
    for (int off = 1; off < 1024; off <<= 1) {
        int v = 0;
        if (t >= off) v = sums[t - off];
        __syncthreads();
        if (t >= off) sums[t] += v;
        __syncthreads();
    }
    const int chunk_off = (t == 0) ? 0 : sums[t - 1];
#pragma unroll
    for (int i = 0; i < 32; ++i) {
        int v = chunk_off + local[i];
        g_rowptr[base + i] = v;
        g_cursor[base + i] = v;
    }
    if (t == 1023) g_rowptr[NNODES] = sums[1023];
}

// ---------------- scatter edge ids into CSR order ----------------
__global__ void scatter_kernel(const int* __restrict__ dst) {
    int e = blockIdx.x * blockDim.x + threadIdx.x;
    if (e >= NEDGES) return;
    int d = dst[e];
    int p = atomicAdd(&g_cursor[d], 1);
    g_perm[p] = e;
}

// ---------------- build fused weight matrix [D, NCOLS] = [basis_flat | root] ------
__global__ void build_bcat_kernel(const float* __restrict__ basis,
                                  const float* __restrict__ root) {
    int idx = blockIdx.x * blockDim.x + threadIdx.x;
    if (idx >= D * NCOLS) return;
    int i = idx / NCOLS;
    int c = idx % NCOLS;
    float v;
    if (c < NBASES * D) {
        int b = c >> 8;          // D == 256
        int o = c & 255;
        v = basis[((size_t)b * D + i) * D + o];   // basis[b, i, o]
    } else {
        v = root[i * D + (c - NBASES * D)];
    }
    g_Bcat[idx] = v;
}

// ---------------- fp32 GEMM: g_z[M, NCOLS] = A[M, D] @ g_Bcat[D, NCOLS] -----------
// 128x128 tile, BK=16, 256 threads, 8x8 per thread.
__global__ __launch_bounds__(256) void sgemm_kernel(const float* __restrict__ Aext,
                                                    int use_ext) {
    const float* __restrict__ A = use_ext ? Aext : g_h1;
    const float* __restrict__ B = g_Bcat;
    float* __restrict__ C = g_z;
    const int K = D;
    const int N = NCOLS;

    __shared__ __align__(16) float As[16][128];
    __shared__ __align__(16) float Bs[16][128];

    const int tid = threadIdx.x;
    const int tx = tid & 15;      // N direction
    const int ty = tid >> 4;      // M direction
    const int bx = blockIdx.x * 128;
    const int by = blockIdx.y * 128;

    float acc[8][8] = {};

    const int a_r = tid >> 2;           // 0..63 (two passes: +0, +64)
    const int a_c = (tid & 3) << 2;     // 0,4,8,12
    const int b_r = tid >> 5;           // 0..7  (two passes: +0, +8)
    const int b_c = (tid & 31) << 2;    // 0..124

    for (int k0 = 0; k0 < K; k0 += 16) {
#pragma unroll
        for (int p = 0; p < 2; ++p) {
            float4 v = *(const float4*)(A + (size_t)(by + a_r + p * 64) * K + k0 + a_c);
            As[a_c + 0][a_r + p * 64] = v.x;
            As[a_c + 1][a_r + p * 64] = v.y;
            As[a_c + 2][a_r + p * 64] = v.z;
            As[a_c + 3][a_r + p * 64] = v.w;
        }
#pragma unroll
        for (int p = 0; p < 2; ++p) {
            *(float4*)(&Bs[b_r + p * 8][b_c]) =
                *(const float4*)(B + (size_t)(k0 + b_r + p * 8) * N + bx + b_c);
        }
        __syncthreads();
#pragma unroll
        for (int k = 0; k < 16; ++k) {
            float4 a0 = *(const float4*)(&As[k][ty * 8]);
            float4 a1 = *(const float4*)(&As[k][ty * 8 + 4]);
            float4 b0 = *(const float4*)(&Bs[k][tx * 8]);
            float4 b1 = *(const float4*)(&Bs[k][tx * 8 + 4]);
            float a[8] = {a0.x, a0.y, a0.z, a0.w, a1.x, a1.y, a1.z, a1.w};
            float b[8] = {b0.x, b0.y, b0.z, b0.w, b1.x, b1.y, b1.z, b1.w};
#pragma unroll
            for (int i = 0; i < 8; ++i)
#pragma unroll
                for (int j = 0; j < 8; ++j)
                    acc[i][j] += a[i] * b[j];
        }
        __syncthreads();
    }
#pragma unroll
    for (int i = 0; i < 8; ++i) {
        float* Cp = C + (size_t)(by + ty * 8 + i) * N + bx + tx * 8;
        *(float4*)(Cp)     = make_float4(acc[i][0], acc[i][1], acc[i][2], acc[i][3]);
        *(float4*)(Cp + 4) = make_float4(acc[i][4], acc[i][5], acc[i][6], acc[i][7]);
    }
}

// ---------------- atomic-free aggregation: one block (64 threads) per dst ---------
// out[dst, :] = sum_{e: dst} (sum_b comp[rel_e,b]/cnt[rel_e,dst] * xb[src_e, b, :])
//               + root_proj[dst, :] + bias[:]   (optional ReLU)
__global__ void aggregate_kernel(const int* __restrict__ src,
                                 const int* __restrict__ rel,
                                 const float* __restrict__ comp,
                                 const float* __restrict__ bias,
                                 float* __restrict__ out_ext,
                                 int layer) {
    const int dst = blockIdx.x;
    const int t = threadIdx.x;   // 64 threads, each handles a float4 (4 cols)
    __shared__ float scomp[NREL * NBASES];
    if (t < NREL * NBASES) scomp[t] = comp[t];
    __syncthreads();

    float4 acc = make_float4(0.f, 0.f, 0.f, 0.f);
    const int beg = g_rowptr[dst];
    const int end = g_rowptr[dst + 1];
    for (int e = beg; e < end; ++e) {
        const int eid = g_perm[e];
        const int s = __ldg(&src[eid]);
        const int r = __ldg(&rel[eid]);
        const float inv = 1.0f / (float)g_cnt[r * NNODES + dst];
        const float w0 = scomp[r * 4 + 0] * inv;
        const float w1 = scomp[r * 4 + 1] * inv;
        const float w2 = scomp[r * 4 + 2] * inv;
        const float w3 = scomp[r * 4 + 3] * inv;
        const float4* xb = (const float4*)(g_z + (size_t)s * NCOLS);
        float4 v0 = __ldg(&xb[t]);
        float4 v1 = __ldg(&xb[64 + t]);
        float4 v2 = __ldg(&xb[128 + t]);
        float4 v3 = __ldg(&xb[192 + t]);
        acc.x += w0 * v0.x + w1 * v1.x + w2 * v2.x + w3 * v3.x;
        acc.y += w0 * v0.y + w1 * v1.y + w2 * v2.y + w3 * v3.y;
        acc.z += w0 * v0.z + w1 * v1.z + w2 * v2.z + w3 * v3.z;
        acc.w += w0 * v0.w + w1 * v1.w + w2 * v2.w + w3 * v3.w;
    }
    const float4 base = __ldg((const float4*)(g_z + (size_t)dst * NCOLS + NBASES * D) + t);
    const float4 bi = __ldg((const float4*)bias + t);
    float4 o;
    o.x = acc.x + base.x + bi.x;
    o.y = acc.y + base.y + bi.y;
    o.z = acc.z + base.z + bi.z;
    o.w = acc.w + base.w + bi.w;
    if (layer == 0) {
        o.x = fmaxf(o.x, 0.f);
        o.y = fmaxf(o.y, 0.f);
        o.z = fmaxf(o.z, 0.f);
        o.w = fmaxf(o.w, 0.f);
        ((float4*)g_h1)[(size_t)dst * 64 + t] = o;
    } else {
        ((float4*)out_ext)[(size_t)dst * 64 + t] = o;
    }
}

// ---------------- launch ----------------
extern "C" void kernel_launch(void* const* d_in, const int* in_sizes, int n_in,
                              void* d_out, int out_size) {
    const float* x      = (const float*)d_in[0];        // [16,2048,256] == [32768,256]
    const int*   edges  = (const int*)d_in[3];          // [2, E]
    const int*   rel    = (const int*)d_in[4];          // [E]
    const float* basis0 = (const float*)d_in[5];
    const float* comp0  = (const float*)d_in[6];
    const float* root0  = (const float*)d_in[7];
    const float* bias0  = (const float*)d_in[8];
    const float* basis1 = (const float*)d_in[9];
    const float* comp1  = (const float*)d_in[10];
    const float* root1  = (const float*)d_in[11];
    const float* bias1  = (const float*)d_in[12];
    float* out = (float*)d_out;

    const int* src = edges;
    const int* dst = edges + NEDGES;

    // CSR + normalization counts (shared by both layers)
    zero_counts_kernel<<<1408, 256>>>();
    hist_kernel<<<(NEDGES + 255) / 256, 256>>>(dst, rel);
    scan_kernel<<<1, 1024>>>();
    scatter_kernel<<<(NEDGES + 255) / 256, 256>>>(dst);

    dim3 gemm_grid(NCOLS / 128, NNODES / 128);

    // Layer 0: x -> h1 (ReLU)
    build_bcat_kernel<<<(D * NCOLS + 255) / 256, 256>>>(basis0, root0);
    sgemm_kernel<<<gemm_grid, 256>>>(x, 1);
    aggregate_kernel<<<NNODES, 64>>>(src, rel, comp0, bias0, nullptr, 0);

    // Layer 1: h1 -> out
    build_bcat_kernel<<<(D * NCOLS + 255) / 256, 256>>>(basis1, root1);
    sgemm_kernel<<<gemm_grid, 256>>>(nullptr, 0);
    aggregate_kernel<<<NNODES, 64>>>(src, rel, comp1, bias1, out, 1);
}

// round 3
// speedup vs baseline: 1.0004x; 1.0003x over previous
#include <cuda_runtime.h>
#include <cuda_bf16.h>

#define D 256
#define NNODES 32768
#define NREL 10
#define NBASES 4
#define NEDGES 524288
#define NCOLS 1280   // NBASES*D (basis projections) + D (root projection)

// ---------------- scratch (static device allocations; no cudaMalloc) ----------------
__device__ float g_z[(size_t)NNODES * NCOLS];     // 160 MB: per-node [xb(1024) | root(256)]
__device__ float g_h1[(size_t)NNODES * D];        // 32 MB: hidden activations
__device__ float g_Bcat[D * NCOLS];               // fused weight matrix per layer
__device__ int   g_cnt[NREL * NNODES];            // per-(rel,dst) edge counts
__device__ int   g_deg[NNODES];                   // per-dst degree
__device__ int   g_rowptr[NNODES + 1];            // CSR row pointers (by dst)
__device__ int   g_cursor[NNODES];                // scatter cursors
__device__ int   g_perm[NEDGES];                  // CSR edge permutation

// ---------------- zero the histogram buffers ----------------
__global__ void zero_counts_kernel() {
    int i = blockIdx.x * blockDim.x + threadIdx.x;
    int total = NNODES + NREL * NNODES;
    for (; i < total; i += gridDim.x * blockDim.x) {
        if (i < NNODES) g_deg[i] = 0;
        else            g_cnt[i - NNODES] = 0;
    }
}

// ---------------- histogram: degree per dst + count per (rel,dst) ----------------
__global__ void hist_kernel(const int* __restrict__ dst, const int* __restrict__ rel) {
    int e = blockIdx.x * blockDim.x + threadIdx.x;
    if (e >= NEDGES) return;
    int d = dst[e];
    int r = rel[e];
    atomicAdd(&g_deg[d], 1);
    atomicAdd(&g_cnt[r * NNODES + d], 1);
}

// ---------------- exclusive scan of g_deg -> g_rowptr / g_cursor (single block) ----
__global__ void scan_kernel() {
    __shared__ int sums[1024];
    const int t = threadIdx.x;           // 1024 threads, 32 elements each
    const int base = t * 32;
    int local[32];
    int s = 0;
#pragma unroll
    for (int i = 0; i < 32; ++i) { local[i] = s; s += g_deg[base + i]; }
    sums[t] = s;
    __syncthreads();
    // Hillis-Steele inclusive scan over 1024 partials
    for (int off = 1; off < 1024; off <<= 1) {
        int v = 0;
        if (t >= off) v = sums[t - off];
        __syncthreads();
        if (t >= off) sums[t] += v;
        __syncthreads();
    }
    const int chunk_off = (t == 0) ? 0 : sums[t - 1];
#pragma unroll
    for (int i = 0; i < 32; ++i) {
        int v = chunk_off + local[i];
        g_rowptr[base + i] = v;
        g_cursor[base + i] = v;
    }
    if (t == 1023) g_rowptr[NNODES] = sums[1023];
}

// ---------------- scatter edge ids into CSR order ----------------
__global__ void scatter_kernel(const int* __restrict__ dst) {
    int e = blockIdx.x * blockDim.x + threadIdx.x;
    if (e >= NEDGES) return;
    int d = dst[e];
    int p = atomicAdd(&g_cursor[d], 1);
    g_perm[p] = e;
}

// ---------------- build fused weight matrix [D, NCOLS] = [basis_flat | root] ------
__global__ void build_bcat_kernel(const float* __restrict__ basis,
                                  const float* __restrict__ root) {
    int idx = blockIdx.x * blockDim.x + threadIdx.x;
    if (idx >= D * NCOLS) return;
    int i = idx / NCOLS;
    int c = idx % NCOLS;
    float v;
    if (c < NBASES * D) {
        int b = c >> 8;          // D == 256
        int o = c & 255;
        v = basis[((size_t)b * D + i) * D + o];   // basis[b, i, o]
    } else {
        v = root[i * D + (c - NBASES * D)];
    }
    g_Bcat[idx] = v;
}

// ---------------- fp32 GEMM: g_z[M, NCOLS] = A[M, D] @ g_Bcat[D, NCOLS] -----------
// 128x128 tile, BK=16, 256 threads, 8x8 per thread.
__global__ __launch_bounds__(256) void sgemm_kernel(const float* __restrict__ Aext,
                                                    int use_ext) {
    const float* __restrict__ A = use_ext ? Aext : g_h1;
    const float* __restrict__ B = g_Bcat;
    float* __restrict__ C = g_z;
    const int K = D;
    const int N = NCOLS;

    __shared__ __align__(16) float As[16][128];
    __shared__ __align__(16) float Bs[16][128];

    const int tid = threadIdx.x;
    const int tx = tid & 15;      // N direction
    const int ty = tid >> 4;      // M direction
    const int bx = blockIdx.x * 128;
    const int by = blockIdx.y * 128;

    float acc[8][8] = {};

    const int a_r = tid >> 2;           // 0..63 (two passes: +0, +64)
    const int a_c = (tid & 3) << 2;     // 0,4,8,12
    const int b_r = tid >> 5;           // 0..7  (two passes: +0, +8)
    const int b_c = (tid & 31) << 2;    // 0..124

    for (int k0 = 0; k0 < K; k0 += 16) {
#pragma unroll
        for (int p = 0; p < 2; ++p) {
            float4 v = *(const float4*)(A + (size_t)(by + a_r + p * 64) * K + k0 + a_c);
            As[a_c + 0][a_r + p * 64] = v.x;
            As[a_c + 1][a_r + p * 64] = v.y;
            As[a_c + 2][a_r + p * 64] = v.z;
            As[a_c + 3][a_r + p * 64] = v.w;
        }
#pragma unroll
        for (int p = 0; p < 2; ++p) {
            *(float4*)(&Bs[b_r + p * 8][b_c]) =
                *(const float4*)(B + (size_t)(k0 + b_r + p * 8) * N + bx + b_c);
        }
        __syncthreads();
#pragma unroll
        for (int k = 0; k < 16; ++k) {
            float4 a0 = *(const float4*)(&As[k][ty * 8]);
            float4 a1 = *(const float4*)(&As[k][ty * 8 + 4]);
            float4 b0 = *(const float4*)(&Bs[k][tx * 8]);
            float4 b1 = *(const float4*)(&Bs[k][tx * 8 + 4]);
            float a[8] = {a0.x, a0.y, a0.z, a0.w, a1.x, a1.y, a1.z, a1.w};
            float b[8] = {b0.x, b0.y, b0.z, b0.w, b1.x, b1.y, b1.z, b1.w};
#pragma unroll
            for (int i = 0; i < 8; ++i)
#pragma unroll
                for (int j = 0; j < 8; ++j)
                    acc[i][j] += a[i] * b[j];
        }
        __syncthreads();
    }
#pragma unroll
    for (int i = 0; i < 8; ++i) {
        float* Cp = C + (size_t)(by + ty * 8 + i) * N + bx + tx * 8;
        *(float4*)(Cp)     = make_float4(acc[i][0], acc[i][1], acc[i][2], acc[i][3]);
        *(float4*)(Cp + 4) = make_float4(acc[i][4], acc[i][5], acc[i][6], acc[i][7]);
    }
}

// ---------------- atomic-free aggregation: one block (64 threads) per dst ---------
// out[dst, :] = sum_{e: dst} (sum_b comp[rel_e,b]/cnt[rel_e,dst] * xb[src_e, b, :])
//               + root_proj[dst, :] + bias[:]   (optional ReLU)
__global__ void aggregate_kernel(const int* __restrict__ src,
                                 const int* __restrict__ rel,
                                 const float* __restrict__ comp,
                                 const float* __restrict__ bias,
                                 float* __restrict__ out_ext,
                                 int layer) {
    const int dst = blockIdx.x;
    const int t = threadIdx.x;   // 64 threads, each handles a float4 (4 cols)
    __shared__ float scomp[NREL * NBASES];
    if (t < NREL * NBASES) scomp[t] = comp[t];
    __syncthreads();

    float4 acc = make_float4(0.f, 0.f, 0.f, 0.f);
    const int beg = g_rowptr[dst];
    const int end = g_rowptr[dst + 1];
    for (int e = beg; e < end; ++e) {
        const int eid = g_perm[e];
        const int s = __ldg(&src[eid]);
        const int r = __ldg(&rel[eid]);
        const float inv = 1.0f / (float)g_cnt[r * NNODES + dst];
        const float w0 = scomp[r * 4 + 0] * inv;
        const float w1 = scomp[r * 4 + 1] * inv;
        const float w2 = scomp[r * 4 + 2] * inv;
        const float w3 = scomp[r * 4 + 3] * inv;
        const float4* xb = (const float4*)(g_z + (size_t)s * NCOLS);
        float4 v0 = __ldg(&xb[t]);
        float4 v1 = __ldg(&xb[64 + t]);
        float4 v2 = __ldg(&xb[128 + t]);
        float4 v3 = __ldg(&xb[192 + t]);
        acc.x += w0 * v0.x + w1 * v1.x + w2 * v2.x + w3 * v3.x;
        acc.y += w0 * v0.y + w1 * v1.y + w2 * v2.y + w3 * v3.y;
        acc.z += w0 * v0.z + w1 * v1.z + w2 * v2.z + w3 * v3.z;
        acc.w += w0 * v0.w + w1 * v1.w + w2 * v2.w + w3 * v3.w;
    }
    const float4 base = __ldg((const float4*)(g_z + (size_t)dst * NCOLS + NBASES * D) + t);
    const float4 bi = __ldg((const float4*)bias + t);
    float4 o;
    o.x = acc.x + base.x + bi.x;
    o.y = acc.y + base.y + bi.y;
    o.z = acc.z + base.z + bi.z;
    o.w = acc.w + base.w + bi.w;
    if (layer == 0) {
        o.x = fmaxf(o.x, 0.f);
        o.y = fmaxf(o.y, 0.f);
        o.z = fmaxf(o.z, 0.f);
        o.w = fmaxf(o.w, 0.f);
        ((float4*)g_h1)[(size_t)dst * 64 + t] = o;
    } else {
        ((float4*)out_ext)[(size_t)dst * 64 + t] = o;
    }
}

// ---------------- launch ----------------
extern "C" void kernel_launch(void* const* d_in, const int* in_sizes, int n_in,
                              void* d_out, int out_size) {
    const float* x      = (const float*)d_in[0];        // [16,2048,256] == [32768,256]
    const int*   edges  = (const int*)d_in[3];          // [2, E]
    const int*   rel    = (const int*)d_in[4];          // [E]
    const float* basis0 = (const float*)d_in[5];
    const float* comp0  = (const float*)d_in[6];
    const float* root0  = (const float*)d_in[7];
    const float* bias0  = (const float*)d_in[8];
    const float* basis1 = (const float*)d_in[9];
    const float* comp1  = (const float*)d_in[10];
    const float* root1  = (const float*)d_in[11];
    const float* bias1  = (const float*)d_in[12];
    float* out = (float*)d_out;

    const int* src = edges;
    const int* dst = edges + NEDGES;

    // CSR + normalization counts (shared by both layers)
    zero_counts_kernel<<<1408, 256>>>();
    hist_kernel<<<(NEDGES + 255) / 256, 256>>>(dst, rel);
    scan_kernel<<<1, 1024>>>();
    scatter_kernel<<<(NEDGES + 255) / 256, 256>>>(dst);

    dim3 gemm_grid(NCOLS / 128, NNODES / 128);

    // Layer 0: x -> h1 (ReLU)
    build_bcat_kernel<<<(D * NCOLS + 255) / 256, 256>>>(basis0, root0);
    sgemm_kernel<<<gemm_grid, 256>>>(x, 1);
    aggregate_kernel<<<NNODES, 64>>>(src, rel, comp0, bias0, nullptr, 0);

    // Layer 1: h1 -> out
    build_bcat_kernel<<<(D * NCOLS + 255) / 256, 256>>>(basis1, root1);
    sgemm_kernel<<<gemm_grid, 256>>>(nullptr, 0);
    aggregate_kernel<<<NNODES, 64>>>(src, rel, comp1, bias1, out, 1);
}

// round 5
// speedup vs baseline: 2.7540x; 2.7528x over previous
#include <cuda_runtime.h>
#include <cuda_bf16.h>
#include <cstdint>

#define D 256
#define NNODES 32768
#define NREL 10
#define NBASES 4
#define NEDGES 524288
#define KTOT 1280          // 1024 (basis-agg part) + 256 (root part)

// ---------------- scratch (static device allocations; no cudaMalloc) ----------------
__device__ float  g_S[(size_t)NNODES * 1024];   // 128 MB: aggregated basis sums (tf32)
__device__ float  g_h1[(size_t)NNODES * D];     // 32 MB: hidden activations (tf32)
__device__ float  g_xr[(size_t)NNODES * D];     // 32 MB: tf32-rounded input x
__device__ float  g_W0[KTOT * D];               // fused weights layer0 (tf32)
__device__ float  g_W1[KTOT * D];               // fused weights layer1 (tf32)
__device__ float  g_bias[2][D];                 // staged biases
__device__ int    g_cnt[NREL * NNODES];
__device__ int    g_deg[NNODES];
__device__ int    g_rowptr[NNODES + 1];
__device__ int    g_cursor[NNODES];
__device__ int    g_csr_src[NEDGES];            // src ids in CSR(dst) order
__device__ float4 g_ew0[NEDGES];                // per-edge basis weights, layer0
__device__ float4 g_ew1[NEDGES];                // per-edge basis weights, layer1

// ---------------- helpers ----------------
__device__ __forceinline__ float tf32r(float x) {
    uint32_t u;
    asm("cvt.rna.tf32.f32 %0, %1;" : "=r"(u) : "f"(x));
    return __uint_as_float(u);
}

__device__ __forceinline__ void cp_async16(uint32_t saddr, const void* gaddr) {
    asm volatile("cp.async.cg.shared.global [%0], [%1], 16;\n" :: "r"(saddr), "l"(gaddr));
}

__device__ __forceinline__ void mma_tf32(float* d, const uint32_t* a, const uint32_t* b) {
    asm volatile(
        "mma.sync.aligned.m16n8k8.row.col.f32.tf32.tf32.f32 "
        "{%0,%1,%2,%3}, {%4,%5,%6,%7}, {%8,%9}, {%0,%1,%2,%3};\n"
        : "+f"(d[0]), "+f"(d[1]), "+f"(d[2]), "+f"(d[3])
        : "r"(a[0]), "r"(a[1]), "r"(a[2]), "r"(a[3]), "r"(b[0]), "r"(b[1]));
}

// ---------------- zero the histogram buffers ----------------
__global__ void zero_counts_kernel() {
    int i = blockIdx.x * blockDim.x + threadIdx.x;
    int total = NNODES + NREL * NNODES;
    for (; i < total; i += gridDim.x * blockDim.x) {
        if (i < NNODES) g_deg[i] = 0;
        else            g_cnt[i - NNODES] = 0;
    }
}

// ---------------- histogram ----------------
__global__ void hist_kernel(const int* __restrict__ dst, const int* __restrict__ rel) {
    int e = blockIdx.x * blockDim.x + threadIdx.x;
    if (e >= NEDGES) return;
    int d = dst[e];
    int r = rel[e];
    atomicAdd(&g_deg[d], 1);
    atomicAdd(&g_cnt[r * NNODES + d], 1);
}

// ---------------- exclusive scan (single block) ----------------
__global__ void scan_kernel() {
    __shared__ int sums[1024];
    const int t = threadIdx.x;
    const int base = t * 32;
    int local[32];
    int s = 0;
#pragma unroll
    for (int i = 0; i < 32; ++i) { local[i] = s; s += g_deg[base + i]; }
    sums[t] = s;
    __syncthreads();
    for (int off = 1; off < 1024; off <<= 1) {
        int v = 0;
        if (t >= off) v = sums[t - off];
        __syncthreads();
        if (t >= off) sums[t] += v;
        __syncthreads();
    }
    const int chunk_off = (t == 0) ? 0 : sums[t - 1];
#pragma unroll
    for (int i = 0; i < 32; ++i) {
        int v = chunk_off + local[i];
        g_rowptr[base + i] = v;
        g_cursor[base + i] = v;
    }
    if (t == 1023) g_rowptr[NNODES] = sums[1023];
}

// ---------------- scatter: CSR order src + precomputed per-edge weights -----------
__global__ void scatter_kernel(const int* __restrict__ src, const int* __restrict__ dst,
                               const int* __restrict__ rel,
                               const float* __restrict__ comp0,
                               const float* __restrict__ comp1) {
    int e = blockIdx.x * blockDim.x + threadIdx.x;
    if (e >= NEDGES) return;
    int d = dst[e];
    int r = rel[e];
    int p = atomicAdd(&g_cursor[d], 1);
    float inv = 1.0f / (float)g_cnt[r * NNODES + d];
    g_csr_src[p] = src[e];
    g_ew0[p] = make_float4(comp0[r * 4 + 0] * inv, comp0[r * 4 + 1] * inv,
                           comp0[r * 4 + 2] * inv, comp0[r * 4 + 3] * inv);
    g_ew1[p] = make_float4(comp1[r * 4 + 0] * inv, comp1[r * 4 + 1] * inv,
                           comp1[r * 4 + 2] * inv, comp1[r * 4 + 3] * inv);
}

// ---------------- round input x to tf32 ----------------
__global__ void round_x_kernel(const float* __restrict__ x) {
    int i = blockIdx.x * blockDim.x + threadIdx.x;
    if (i >= NNODES * D) return;
    g_xr[i] = tf32r(x[i]);
}

// ---------------- build fused weight matrices [KTOT, D], tf32-rounded --------------
__global__ void build_w_kernel(const float* __restrict__ basis0, const float* __restrict__ root0,
                               const float* __restrict__ basis1, const float* __restrict__ root1) {
    int idx = blockIdx.x * blockDim.x + threadIdx.x;
    if (idx >= KTOT * D) return;
    int k = idx / D;
    int n = idx % D;
    float v0, v1;
    if (k < NBASES * D) {
        int b = k >> 8;
        int i = k & 255;
        v0 = basis0[((size_t)b * D + i) * D + n];
        v1 = basis1[((size_t)b * D + i) * D + n];
    } else {
        v0 = root0[(size_t)(k - NBASES * D) * D + n];
        v1 = root1[(size_t)(k - NBASES * D) * D + n];
    }
    g_W0[idx] = tf32r(v0);
    g_W1[idx] = tf32r(v1);
}

// ---------------- bias staging ----------------
__global__ void copy_bias_kernel(const float* __restrict__ bias0,
                                 const float* __restrict__ bias1) {
    int i = threadIdx.x;
    if (i < D) { g_bias[0][i] = bias0[i]; g_bias[1][i] = bias1[i]; }
}

// ---------------- aggregation in input space: S[dst, b, :] = sum_e w_b(e) feat[src] --
// One block (64 threads) per dst node; gather table is 32 MB -> L2-resident.
__global__ void aggregate_kernel(int layer) {
    const float4* __restrict__ feat = (const float4*)(layer ? g_h1 : g_xr);
    const float4* __restrict__ ew   = layer ? g_ew1 : g_ew0;
    const int dst = blockIdx.x;
    const int t = threadIdx.x;  // 0..63, each owns 4 columns (float4)

    float4 a0 = {0.f, 0.f, 0.f, 0.f}, a1 = a0, a2 = a0, a3 = a0;
    const int beg = g_rowptr[dst];
    const int end = g_rowptr[dst + 1];
    for (int e = beg; e < end; ++e) {
        const int s = __ldg(&g_csr_src[e]);
        const float4 w = __ldg(&ew[e]);
        const float4 v = __ldg(&feat[(size_t)s * 64 + t]);
        a0.x += w.x * v.x; a0.y += w.x * v.y; a0.z += w.x * v.z; a0.w += w.x * v.w;
        a1.x += w.y * v.x; a1.y += w.y * v.y; a1.z += w.y * v.z; a1.w += w.y * v.w;
        a2.x += w.z * v.x; a2.y += w.z * v.y; a2.z += w.z * v.z; a2.w += w.z * v.w;
        a3.x += w.w * v.x; a3.y += w.w * v.y; a3.z += w.w * v.z; a3.w += w.w * v.w;
    }
    float4* Sp = (float4*)(g_S + (size_t)dst * 1024);
    Sp[t]       = make_float4(tf32r(a0.x), tf32r(a0.y), tf32r(a0.z), tf32r(a0.w));
    Sp[64 + t]  = make_float4(tf32r(a1.x), tf32r(a1.y), tf32r(a1.z), tf32r(a1.w));
    Sp[128 + t] = make_float4(tf32r(a2.x), tf32r(a2.y), tf32r(a2.z), tf32r(a2.w));
    Sp[192 + t] = make_float4(tf32r(a3.x), tf32r(a3.y), tf32r(a3.z), tf32r(a3.w));
}

// ---------------- tf32 tensor-core GEMM ------------------------------------------
// C[32768, 256] = A[32768, 1280] @ W[1280, 256] (+bias, opt relu)
// A = [g_S (k<1024) | R (k>=1024)], all operands pre-rounded to tf32.
// Block: 128x128x32, 256 threads (8 warps as 2(M) x 4(N), warp tile 64x32).
#define LDA 36
#define LDB 136
#define NIT (KTOT / 32)
#define GEMM_SMEM ((2 * (128 * LDA + 32 * LDB)) * 4)

__global__ __launch_bounds__(256) void gemm_tf32_kernel(float* __restrict__ out_ext, int layer) {
    extern __shared__ float smem[];
    float* sA = smem;                       // 2 x [128][LDA]
    float* sB = smem + 2 * 128 * LDA;       // 2 x [32][LDB]

    const float* __restrict__ Sg = g_S;
    const float* __restrict__ Rg = layer ? g_h1 : g_xr;
    const float* __restrict__ Wg = layer ? g_W1 : g_W0;

    const int tid  = threadIdx.x;
    const int warp = tid >> 5, lane = tid & 31;
    const int g  = lane >> 2, t4 = lane & 3;
    const int wm = warp >> 2, wn = warp & 3;
    const int by = blockIdx.y * 128;
    const int bx = blockIdx.x * 128;

    // gmem->smem mapping
    const int ar = tid >> 3;            // 0..31 (A row within pass)
    const int ac = (tid & 7) * 4;       // A col (k) 0..28
    const int bk = tid >> 5;            // 0..7  (B row k within pass)
    const int bn = (tid & 31) * 4;      // B col 0..124

    float acc[4][4][4];
#pragma unroll
    for (int i = 0; i < 4; ++i)
#pragma unroll
        for (int j = 0; j < 4; ++j)
#pragma unroll
            for (int q = 0; q < 4; ++q) acc[i][j][q] = 0.f;

    auto issue = [&](int it, int buf) {
        const int k0 = it * 32;
        const float* Abase;
        int astr;
        if (k0 < 1024) { Abase = Sg + (size_t)by * 1024 + k0; astr = 1024; }
        else           { Abase = Rg + (size_t)by * 256 + (k0 - 1024); astr = 256; }
        float* dA = sA + buf * 128 * LDA;
#pragma unroll
        for (int p = 0; p < 4; ++p) {
            int r = ar + p * 32;
            cp_async16((uint32_t)__cvta_generic_to_shared(&dA[r * LDA + ac]),
                       Abase + (size_t)r * astr + ac);
        }
        float* dB = sB + buf * 32 * LDB;
#pragma unroll
        for (int p = 0; p < 4; ++p) {
            int k = bk + p * 8;
            cp_async16((uint32_t)__cvta_generic_to_shared(&dB[k * LDB + bn]),
                       Wg + (size_t)(k0 + k) * 256 + bx + bn);
        }
        asm volatile("cp.async.commit_group;\n" ::);
    };

    issue(0, 0);

    for (int it = 0; it < NIT; ++it) {
        asm volatile("cp.async.wait_group 0;\n" ::);
        __syncthreads();
        if (it + 1 < NIT) issue(it + 1, (it + 1) & 1);

        const float* cA = sA + (it & 1) * 128 * LDA;
        const float* cB = sB + (it & 1) * 32 * LDB;

#pragma unroll
        for (int kk = 0; kk < 32; kk += 8) {
            uint32_t af[4][4], bf[4][2];
#pragma unroll
            for (int mi = 0; mi < 4; ++mi) {
                const int m = wm * 64 + mi * 16 + g;
                af[mi][0] = __float_as_uint(cA[m * LDA + kk + t4]);
                af[mi][1] = __float_as_uint(cA[(m + 8) * LDA + kk + t4]);
                af[mi][2] = __float_as_uint(cA[m * LDA + kk + t4 + 4]);
                af[mi][3] = __float_as_uint(cA[(m + 8) * LDA + kk + t4 + 4]);
            }
#pragma unroll
            for (int ni = 0; ni < 4; ++ni) {
                const int n = wn * 32 + ni * 8 + g;
                bf[ni][0] = __float_as_uint(cB[(kk + t4) * LDB + n]);
                bf[ni][1] = __float_as_uint(cB[(kk + t4 + 4) * LDB + n]);
            }
#pragma unroll
            for (int mi = 0; mi < 4; ++mi)
#pragma unroll
                for (int ni = 0; ni < 4; ++ni)
                    mma_tf32(acc[mi][ni], af[mi], bf[ni]);
        }
    }

    // epilogue
    float* Cout = layer ? out_ext : g_h1;
#pragma unroll
    for (int mi = 0; mi < 4; ++mi) {
        const int row = by + wm * 64 + mi * 16 + g;
#pragma unroll
        for (int ni = 0; ni < 4; ++ni) {
            const int col = bx + wn * 32 + ni * 8 + t4 * 2;
            const float b0 = g_bias[layer][col];
            const float b1 = g_bias[layer][col + 1];
            float v0 = acc[mi][ni][0] + b0, v1 = acc[mi][ni][1] + b1;
            float v2 = acc[mi][ni][2] + b0, v3 = acc[mi][ni][3] + b1;
            if (layer == 0) {
                v0 = tf32r(fmaxf(v0, 0.f)); v1 = tf32r(fmaxf(v1, 0.f));
                v2 = tf32r(fmaxf(v2, 0.f)); v3 = tf32r(fmaxf(v3, 0.f));
            }
            *(float2*)(Cout + (size_t)row * 256 + col)       = make_float2(v0, v1);
            *(float2*)(Cout + (size_t)(row + 8) * 256 + col) = make_float2(v2, v3);
        }
    }
}

// ---------------- launch ----------------
extern "C" void kernel_launch(void* const* d_in, const int* in_sizes, int n_in,
                              void* d_out, int out_size) {
    const float* x      = (const float*)d_in[0];
    const int*   edges  = (const int*)d_in[3];
    const int*   rel    = (const int*)d_in[4];
    const float* basis0 = (const float*)d_in[5];
    const float* comp0  = (const float*)d_in[6];
    const float* root0  = (const float*)d_in[7];
    const float* bias0  = (const float*)d_in[8];
    const float* basis1 = (const float*)d_in[9];
    const float* comp1  = (const float*)d_in[10];
    const float* root1  = (const float*)d_in[11];
    const float* bias1  = (const float*)d_in[12];
    float* out = (float*)d_out;

    const int* src = edges;
    const int* dst = edges + NEDGES;

    cudaFuncSetAttribute(gemm_tf32_kernel,
                         cudaFuncAttributeMaxDynamicSharedMemorySize, GEMM_SMEM);

    // CSR + per-edge weights (shared by both layers)
    zero_counts_kernel<<<1408, 256>>>();
    hist_kernel<<<(NEDGES + 255) / 256, 256>>>(dst, rel);
    scan_kernel<<<1, 1024>>>();
    scatter_kernel<<<(NEDGES + 255) / 256, 256>>>(src, dst, rel, comp0, comp1);

    // tf32 operand prep
    round_x_kernel<<<(NNODES * D + 255) / 256, 256>>>(x);
    build_w_kernel<<<(KTOT * D + 255) / 256, 256>>>(basis0, root0, basis1, root1);
    copy_bias_kernel<<<1, D>>>(bias0, bias1);

    dim3 ggrid(2, NNODES / 128);

    // Layer 0: aggregate(x) -> S; [S|x] @ W0 + bias0, ReLU -> h1
    aggregate_kernel<<<NNODES, 64>>>(0);
    gemm_tf32_kernel<<<ggrid, 256, GEMM_SMEM>>>(nullptr, 0);

    // Layer 1: aggregate(h1) -> S; [S|h1] @ W1 + bias1 -> out
    aggregate_kernel<<<NNODES, 64>>>(1);
    gemm_tf32_kernel<<<ggrid, 256, GEMM_SMEM>>>(out, 1);
}

// round 8
// speedup vs baseline: 3.1213x; 1.1334x over previous
#include <cuda_runtime.h>
#include <cuda_fp16.h>
#include <cstdint>

#define D 256
#define NNODES 32768
#define NREL 10
#define NBASES 4
#define NEDGES 524288
#define KTOT 1280          // 1024 (basis-agg part) + 256 (root part)

// ---------------- scratch (static device allocations; no cudaMalloc) ----------------
__device__ __half  g_Sh[(size_t)NNODES * 1024];  // 64 MB: aggregated basis sums (fp16)
__device__ __half  g_h1h[(size_t)NNODES * D];    // 16 MB: hidden activations (fp16)
__device__ __half  g_xh[(size_t)NNODES * D];     // 16 MB: fp16 input x
__device__ __half  g_W0T[D * KTOT];              // W^T layer0: [n=256][k=1280] (fp16)
__device__ __half  g_W1T[D * KTOT];              // W^T layer1
__device__ float   g_bias[2][D];
__device__ int     g_cnt[NREL * NNODES];
__device__ int     g_deg[NNODES];
__device__ int     g_rowptr[NNODES + 1];
__device__ int     g_cursor[NNODES];
__device__ int     g_csr_src[NEDGES];
__device__ float4  g_ew0[NEDGES];
__device__ float4  g_ew1[NEDGES];

// ---------------- helpers ----------------
__device__ __forceinline__ void cp_async16(uint32_t saddr, const void* gaddr) {
    asm volatile("cp.async.cg.shared.global [%0], [%1], 16;\n" :: "r"(saddr), "l"(gaddr));
}

__device__ __forceinline__ void mma_fp16(float* d, const uint32_t* a, const uint32_t* b) {
    asm volatile(
        "mma.sync.aligned.m16n8k16.row.col.f32.f16.f16.f32 "
        "{%0,%1,%2,%3}, {%4,%5,%6,%7}, {%8,%9}, {%0,%1,%2,%3};\n"
        : "+f"(d[0]), "+f"(d[1]), "+f"(d[2]), "+f"(d[3])
        : "r"(a[0]), "r"(a[1]), "r"(a[2]), "r"(a[3]), "r"(b[0]), "r"(b[1]));
}

__device__ __forceinline__ uint2 pack4h(float x, float y, float z, float w) {
    __half2 p0 = __floats2half2_rn(x, y);
    __half2 p1 = __floats2half2_rn(z, w);
    uint2 o;
    o.x = *(uint32_t*)&p0;
    o.y = *(uint32_t*)&p1;
    return o;
}

// ---------------- zero the histogram buffers ----------------
__global__ void zero_counts_kernel() {
    int i = blockIdx.x * blockDim.x + threadIdx.x;
    int total = NNODES + NREL * NNODES;
    for (; i < total; i += gridDim.x * blockDim.x) {
        if (i < NNODES) g_deg[i] = 0;
        else            g_cnt[i - NNODES] = 0;
    }
}

// ---------------- histogram ----------------
__global__ void hist_kernel(const int* __restrict__ dst, const int* __restrict__ rel) {
    int e = blockIdx.x * blockDim.x + threadIdx.x;
    if (e >= NEDGES) return;
    int d = dst[e];
    int r = rel[e];
    atomicAdd(&g_deg[d], 1);
    atomicAdd(&g_cnt[r * NNODES + d], 1);
}

// ---------------- exclusive scan (single block) ----------------
__global__ void scan_kernel() {
    __shared__ int sums[1024];
    const int t = threadIdx.x;
    const int base = t * 32;
    int local[32];
    int s = 0;
#pragma unroll
    for (int i = 0; i < 32; ++i) { local[i] = s; s += g_deg[base + i]; }
    sums[t] = s;
    __syncthreads();
    for (int off = 1; off < 1024; off <<= 1) {
        int v = 0;
        if (t >= off) v = sums[t - off];
        __syncthreads();
        if (t >= off) sums[t] += v;
        __syncthreads();
    }
    const int chunk_off = (t == 0) ? 0 : sums[t - 1];
#pragma unroll
    for (int i = 0; i < 32; ++i) {
        int v = chunk_off + local[i];
        g_rowptr[base + i] = v;
        g_cursor[base + i] = v;
    }
    if (t == 1023) g_rowptr[NNODES] = sums[1023];
}

// ---------------- scatter: CSR order src + precomputed per-edge weights -----------
__global__ void scatter_kernel(const int* __restrict__ src, const int* __restrict__ dst,
                               const int* __restrict__ rel,
                               const float* __restrict__ comp0,
                               const float* __restrict__ comp1) {
    int e = blockIdx.x * blockDim.x + threadIdx.x;
    if (e >= NEDGES) return;
    int d = dst[e];
    int r = rel[e];
    int p = atomicAdd(&g_cursor[d], 1);
    float inv = 1.0f / (float)g_cnt[r * NNODES + d];
    g_csr_src[p] = src[e];
    g_ew0[p] = make_float4(comp0[r * 4 + 0] * inv, comp0[r * 4 + 1] * inv,
                           comp0[r * 4 + 2] * inv, comp0[r * 4 + 3] * inv);
    g_ew1[p] = make_float4(comp1[r * 4 + 0] * inv, comp1[r * 4 + 1] * inv,
                           comp1[r * 4 + 2] * inv, comp1[r * 4 + 3] * inv);
}

// ---------------- convert input x to fp16 ----------------
__global__ void round_x_kernel(const float* __restrict__ x) {
    int i = blockIdx.x * blockDim.x + threadIdx.x;
    if (i >= NNODES * D) return;
    g_xh[i] = __float2half_rn(x[i]);
}

// ---------------- build W^T [n=256][k=1280], fp16 ----------------------------------
__global__ void build_wt_kernel(const float* __restrict__ basis0, const float* __restrict__ root0,
                                const float* __restrict__ basis1, const float* __restrict__ root1) {
    int idx = blockIdx.x * blockDim.x + threadIdx.x;
    if (idx >= D * KTOT) return;
    int n = idx / KTOT;
    int k = idx % KTOT;
    float v0, v1;
    if (k < NBASES * D) {
        int b = k >> 8;
        int i = k & 255;
        v0 = basis0[((size_t)b * D + i) * D + n];
        v1 = basis1[((size_t)b * D + i) * D + n];
    } else {
        v0 = root0[(size_t)(k - NBASES * D) * D + n];
        v1 = root1[(size_t)(k - NBASES * D) * D + n];
    }
    g_W0T[idx] = __float2half_rn(v0);
    g_W1T[idx] = __float2half_rn(v1);
}

// ---------------- bias staging ----------------
__global__ void copy_bias_kernel(const float* __restrict__ bias0,
                                 const float* __restrict__ bias1) {
    int i = threadIdx.x;
    if (i < D) { g_bias[0][i] = bias0[i]; g_bias[1][i] = bias1[i]; }
}

// ---------------- aggregation: S[dst, b, :] = sum_e w_b(e) feat[src], unroll x4 -----
// feat rows are fp16 (512B) -> 16 MB table, L2-resident. fp32 accumulate.
__global__ void aggregate_kernel(int layer) {
    const uint2* __restrict__ featv = (const uint2*)(layer ? g_h1h : g_xh); // 4 halfs/thread
    const float4* __restrict__ ew   = layer ? g_ew1 : g_ew0;
    const int dst = blockIdx.x;
    const int t = threadIdx.x;  // 0..63, each owns 4 columns

    float4 a0 = {0.f, 0.f, 0.f, 0.f}, a1 = a0, a2 = a0, a3 = a0;
    const int beg = g_rowptr[dst];
    const int end = g_rowptr[dst + 1];
    int e = beg;

    auto accum = [&](const float4& wt, const uint2& u) {
        float2 f01 = __half22float2(*(const __half2*)&u.x);
        float2 f23 = __half22float2(*(const __half2*)&u.y);
        a0.x += wt.x * f01.x; a0.y += wt.x * f01.y; a0.z += wt.x * f23.x; a0.w += wt.x * f23.y;
        a1.x += wt.y * f01.x; a1.y += wt.y * f01.y; a1.z += wt.y * f23.x; a1.w += wt.y * f23.y;
        a2.x += wt.z * f01.x; a2.y += wt.z * f01.y; a2.z += wt.z * f23.x; a2.w += wt.z * f23.y;
        a3.x += wt.w * f01.x; a3.y += wt.w * f01.y; a3.z += wt.w * f23.x; a3.w += wt.w * f23.y;
    };

    for (; e + 4 <= end; e += 4) {
        const int s0 = __ldg(&g_csr_src[e + 0]);
        const int s1 = __ldg(&g_csr_src[e + 1]);
        const int s2 = __ldg(&g_csr_src[e + 2]);
        const int s3 = __ldg(&g_csr_src[e + 3]);
        const uint2 u0 = __ldg(&featv[(size_t)s0 * 64 + t]);
        const uint2 u1 = __ldg(&featv[(size_t)s1 * 64 + t]);
        const uint2 u2 = __ldg(&featv[(size_t)s2 * 64 + t]);
        const uint2 u3 = __ldg(&featv[(size_t)s3 * 64 + t]);
        const float4 w0 = __ldg(&ew[e + 0]);
        const float4 w1 = __ldg(&ew[e + 1]);
        const float4 w2 = __ldg(&ew[e + 2]);
        const float4 w3 = __ldg(&ew[e + 3]);
        accum(w0, u0);
        accum(w1, u1);
        accum(w2, u2);
        accum(w3, u3);
    }
    for (; e < end; ++e) {
        const int s = __ldg(&g_csr_src[e]);
        const float4 wt = __ldg(&ew[e]);
        const uint2 u = __ldg(&featv[(size_t)s * 64 + t]);
        accum(wt, u);
    }

    uint2* Sp = (uint2*)(g_Sh + (size_t)dst * 1024);   // 256 uint2 per row
    Sp[t]       = pack4h(a0.x, a0.y, a0.z, a0.w);
    Sp[64 + t]  = pack4h(a1.x, a1.y, a1.z, a1.w);
    Sp[128 + t] = pack4h(a2.x, a2.y, a2.z, a2.w);
    Sp[192 + t] = pack4h(a3.x, a3.y, a3.z, a3.w);
}

// ---------------- fp16 tensor-core GEMM (mma.sync.m16n8k16) -----------------------
// C[32768,256] = A[32768,1280] @ W[1280,256] (+bias, opt relu)
// A = [g_Sh (k<1024) | feat (k>=1024)] fp16, B = W^T [n][k] fp16, fp32 accum.
// Block 128x128x32, 256 threads (8 warps: 2(M) x 4(N), warp tile 64x32).
#define PITCH 40                          // halfs per smem row (32 + 8 pad) = 80B
#define STAGE_HALFS (2 * 128 * PITCH)     // A[128][40] + B[128][40]
#define NIT (KTOT / 32)
#define GEMM_SMEM (2 * STAGE_HALFS * 2)   // 40960 bytes

__global__ __launch_bounds__(256) void gemm_fp16_kernel(float* __restrict__ out_ext, int layer) {
    extern __shared__ __half smem[];

    const __half* __restrict__ Sg = g_Sh;
    const __half* __restrict__ Rg = layer ? g_h1h : g_xh;
    const __half* __restrict__ WT = layer ? g_W1T : g_W0T;

    const int tid  = threadIdx.x;
    const int warp = tid >> 5, lane = tid & 31;
    const int g  = lane >> 2, t4 = lane & 3;
    const int wm = warp >> 2, wn = warp & 3;
    const int by = blockIdx.y * 128;
    const int bx = blockIdx.x * 128;

    // gmem->smem: each 16B unit = 8 halfs; per operand 512 units (128 rows x 4 chunks)
    const int r16 = tid >> 1;             // 0..127 row (2 threads per row)
    const int c16 = tid & 1;              // chunk 0..1 (+2 in second pass)

    float acc[4][4][4];
#pragma unroll
    for (int i = 0; i < 4; ++i)
#pragma unroll
        for (int j = 0; j < 4; ++j)
#pragma unroll
            for (int q = 0; q < 4; ++q) acc[i][j][q] = 0.f;

    auto issue = [&](int it, int buf) {
        const int k0 = it * 32;
        const __half* Ab;
        int astr;
        if (k0 < 1024) { Ab = Sg + (size_t)by * 1024 + k0; astr = 1024; }
        else           { Ab = Rg + (size_t)by * 256 + (k0 - 1024); astr = 256; }
        __half* dA = smem + buf * STAGE_HALFS;
        __half* dB = dA + 128 * PITCH;
#pragma unroll
        for (int p = 0; p < 2; ++p) {
            int c = c16 + p * 2;          // chunk 0..3 (8 halfs each)
            cp_async16((uint32_t)__cvta_generic_to_shared(&dA[r16 * PITCH + c * 8]),
                       Ab + (size_t)r16 * astr + c * 8);
        }
#pragma unroll
        for (int p = 0; p < 2; ++p) {
            int c = c16 + p * 2;
            cp_async16((uint32_t)__cvta_generic_to_shared(&dB[r16 * PITCH + c * 8]),
                       WT + (size_t)(bx + r16) * KTOT + k0 + c * 8);
        }
        asm volatile("cp.async.commit_group;\n" ::);
    };

    issue(0, 0);

    for (int it = 0; it < NIT; ++it) {
        asm volatile("cp.async.wait_group 0;\n" ::);
        __syncthreads();
        if (it + 1 < NIT) issue(it + 1, (it + 1) & 1);

        const __half* cA = smem + (it & 1) * STAGE_HALFS;
        const __half* cB = cA + 128 * PITCH;

#pragma unroll
        for (int kk = 0; kk < 32; kk += 16) {
            uint32_t af[4][4], bf[4][2];
#pragma unroll
            for (int mi = 0; mi < 4; ++mi) {
                const int m = wm * 64 + mi * 16 + g;
                af[mi][0] = *(const uint32_t*)&cA[m * PITCH + kk + 2 * t4];
                af[mi][1] = *(const uint32_t*)&cA[(m + 8) * PITCH + kk + 2 * t4];
                af[mi][2] = *(const uint32_t*)&cA[m * PITCH + kk + 2 * t4 + 8];
                af[mi][3] = *(const uint32_t*)&cA[(m + 8) * PITCH + kk + 2 * t4 + 8];
            }
#pragma unroll
            for (int ni = 0; ni < 4; ++ni) {
                const int n = wn * 32 + ni * 8 + g;
                bf[ni][0] = *(const uint32_t*)&cB[n * PITCH + kk + 2 * t4];
                bf[ni][1] = *(const uint32_t*)&cB[n * PITCH + kk + 2 * t4 + 8];
            }
#pragma unroll
            for (int mi = 0; mi < 4; ++mi)
#pragma unroll
                for (int ni = 0; ni < 4; ++ni)
                    mma_fp16(acc[mi][ni], af[mi], bf[ni]);
        }
        __syncthreads();
    }

    // epilogue: acc[0],acc[1] -> row cols (2t4, 2t4+1); acc[2],acc[3] -> row+8
#pragma unroll
    for (int mi = 0; mi < 4; ++mi) {
        const int row = by + wm * 64 + mi * 16 + g;
#pragma unroll
        for (int ni = 0; ni < 4; ++ni) {
            const int col = bx + wn * 32 + ni * 8 + t4 * 2;
            const float b0 = g_bias[layer][col];
            const float b1 = g_bias[layer][col + 1];
            float v0 = acc[mi][ni][0] + b0, v1 = acc[mi][ni][1] + b1;
            float v2 = acc[mi][ni][2] + b0, v3 = acc[mi][ni][3] + b1;
            if (layer == 0) {
                v0 = fmaxf(v0, 0.f); v1 = fmaxf(v1, 0.f);
                v2 = fmaxf(v2, 0.f); v3 = fmaxf(v3, 0.f);
                *(__half2*)(g_h1h + (size_t)row * 256 + col)       = __floats2half2_rn(v0, v1);
                *(__half2*)(g_h1h + (size_t)(row + 8) * 256 + col) = __floats2half2_rn(v2, v3);
            } else {
                *(float2*)(out_ext + (size_t)row * 256 + col)       = make_float2(v0, v1);
                *(float2*)(out_ext + (size_t)(row + 8) * 256 + col) = make_float2(v2, v3);
            }
        }
    }
}

// ---------------- launch ----------------
extern "C" void kernel_launch(void* const* d_in, const int* in_sizes, int n_in,
                              void* d_out, int out_size) {
    const float* x      = (const float*)d_in[0];
    const int*   edges  = (const int*)d_in[3];
    const int*   rel    = (const int*)d_in[4];
    const float* basis0 = (const float*)d_in[5];
    const float* comp0  = (const float*)d_in[6];
    const float* root0  = (const float*)d_in[7];
    const float* bias0  = (const float*)d_in[8];
    const float* basis1 = (const float*)d_in[9];
    const float* comp1  = (const float*)d_in[10];
    const float* root1  = (const float*)d_in[11];
    const float* bias1  = (const float*)d_in[12];
    float* out = (float*)d_out;

    const int* src = edges;
    const int* dst = edges + NEDGES;

    // CSR + per-edge weights (shared by both layers)
    zero_counts_kernel<<<1408, 256>>>();
    hist_kernel<<<(NEDGES + 255) / 256, 256>>>(dst, rel);
    scan_kernel<<<1, 1024>>>();
    scatter_kernel<<<(NEDGES + 255) / 256, 256>>>(src, dst, rel, comp0, comp1);

    // fp16 operand prep
    round_x_kernel<<<(NNODES * D + 255) / 256, 256>>>(x);
    build_wt_kernel<<<(D * KTOT + 255) / 256, 256>>>(basis0, root0, basis1, root1);
    copy_bias_kernel<<<1, D>>>(bias0, bias1);

    dim3 ggrid(2, NNODES / 128);

    // Layer 0: aggregate(x) -> S; [S|x] @ W0 + bias0, ReLU -> h1
    aggregate_kernel<<<NNODES, 64>>>(0);
    gemm_fp16_kernel<<<ggrid, 256, GEMM_SMEM>>>(nullptr, 0);

    // Layer 1: aggregate(h1) -> S; [S|h1] @ W1 + bias1 -> out
    aggregate_kernel<<<NNODES, 64>>>(1);
    gemm_fp16_kernel<<<ggrid, 256, GEMM_SMEM>>>(out, 1);
}

// round 9
// speedup vs baseline: 3.4105x; 1.0926x over previous
#include <cuda_runtime.h>
#include <cuda_fp16.h>
#include <cstdint>

#define D 256
#define NNODES 32768
#define NREL 10
#define NBASES 4
#define NEDGES 524288
#define KTOT 1280          // 1024 (basis-agg part) + 256 (root part)

// ---------------- scratch (static device allocations; no cudaMalloc) ----------------
__device__ __half  g_Sh[(size_t)NNODES * 1024];  // 64 MB: aggregated basis sums (fp16)
__device__ __half  g_h1h[(size_t)NNODES * D];    // 16 MB: hidden activations (fp16)
__device__ __half  g_xh[(size_t)NNODES * D];     // 16 MB: fp16 input x
__device__ __half  g_W0T[D * KTOT];              // W^T layer0: [n=256][k=1280] (fp16)
__device__ __half  g_W1T[D * KTOT];              // W^T layer1
__device__ float   g_bias[2][D];
__device__ int     g_cnt[NREL * NNODES];
__device__ int     g_deg[NNODES];
__device__ int     g_rowptr[NNODES + 1];
__device__ int     g_cursor[NNODES];
__device__ int     g_csr_src[NEDGES];
__device__ float4  g_ew0[NEDGES];
__device__ float4  g_ew1[NEDGES];

// ---------------- helpers ----------------
__device__ __forceinline__ void cp_async16(uint32_t saddr, const void* gaddr) {
    asm volatile("cp.async.cg.shared.global [%0], [%1], 16;\n" :: "r"(saddr), "l"(gaddr));
}

__device__ __forceinline__ void mma_fp16(float* d, const uint32_t* a, const uint32_t* b) {
    asm volatile(
        "mma.sync.aligned.m16n8k16.row.col.f32.f16.f16.f32 "
        "{%0,%1,%2,%3}, {%4,%5,%6,%7}, {%8,%9}, {%0,%1,%2,%3};\n"
        : "+f"(d[0]), "+f"(d[1]), "+f"(d[2]), "+f"(d[3])
        : "r"(a[0]), "r"(a[1]), "r"(a[2]), "r"(a[3]), "r"(b[0]), "r"(b[1]));
}

__device__ __forceinline__ void ldsm_x4(uint32_t& r0, uint32_t& r1, uint32_t& r2,
                                        uint32_t& r3, uint32_t saddr) {
    asm volatile("ldmatrix.sync.aligned.m8n8.x4.shared.b16 {%0,%1,%2,%3}, [%4];"
                 : "=r"(r0), "=r"(r1), "=r"(r2), "=r"(r3) : "r"(saddr));
}

__device__ __forceinline__ uint2 pack4h(float x, float y, float z, float w) {
    __half2 p0 = __floats2half2_rn(x, y);
    __half2 p1 = __floats2half2_rn(z, w);
    uint2 o;
    o.x = *(uint32_t*)&p0;
    o.y = *(uint32_t*)&p1;
    return o;
}

// ---------------- zero the histogram buffers ----------------
__global__ void zero_counts_kernel() {
    int i = blockIdx.x * blockDim.x + threadIdx.x;
    int total = NNODES + NREL * NNODES;
    for (; i < total; i += gridDim.x * blockDim.x) {
        if (i < NNODES) g_deg[i] = 0;
        else            g_cnt[i - NNODES] = 0;
    }
}

// ---------------- histogram ----------------
__global__ void hist_kernel(const int* __restrict__ dst, const int* __restrict__ rel) {
    int e = blockIdx.x * blockDim.x + threadIdx.x;
    if (e >= NEDGES) return;
    int d = dst[e];
    int r = rel[e];
    atomicAdd(&g_deg[d], 1);
    atomicAdd(&g_cnt[r * NNODES + d], 1);
}

// ---------------- exclusive scan (single block) ----------------
__global__ void scan_kernel() {
    __shared__ int sums[1024];
    const int t = threadIdx.x;
    const int base = t * 32;
    int local[32];
    int s = 0;
#pragma unroll
    for (int i = 0; i < 32; ++i) { local[i] = s; s += g_deg[base + i]; }
    sums[t] = s;
    __syncthreads();
    for (int off = 1; off < 1024; off <<= 1) {
        int v = 0;
        if (t >= off) v = sums[t - off];
        __syncthreads();
        if (t >= off) sums[t] += v;
        __syncthreads();
    }
    const int chunk_off = (t == 0) ? 0 : sums[t - 1];
#pragma unroll
    for (int i = 0; i < 32; ++i) {
        int v = chunk_off + local[i];
        g_rowptr[base + i] = v;
        g_cursor[base + i] = v;
    }
    if (t == 1023) g_rowptr[NNODES] = sums[1023];
}

// ---------------- scatter: CSR order src + precomputed per-edge weights -----------
__global__ void scatter_kernel(const int* __restrict__ src, const int* __restrict__ dst,
                               const int* __restrict__ rel,
                               const float* __restrict__ comp0,
                               const float* __restrict__ comp1) {
    int e = blockIdx.x * blockDim.x + threadIdx.x;
    if (e >= NEDGES) return;
    int d = dst[e];
    int r = rel[e];
    int p = atomicAdd(&g_cursor[d], 1);
    float inv = 1.0f / (float)g_cnt[r * NNODES + d];
    g_csr_src[p] = src[e];
    g_ew0[p] = make_float4(comp0[r * 4 + 0] * inv, comp0[r * 4 + 1] * inv,
                           comp0[r * 4 + 2] * inv, comp0[r * 4 + 3] * inv);
    g_ew1[p] = make_float4(comp1[r * 4 + 0] * inv, comp1[r * 4 + 1] * inv,
                           comp1[r * 4 + 2] * inv, comp1[r * 4 + 3] * inv);
}

// ---------------- convert input x to fp16 ----------------
__global__ void round_x_kernel(const float* __restrict__ x) {
    int i = blockIdx.x * blockDim.x + threadIdx.x;
    if (i >= NNODES * D) return;
    g_xh[i] = __float2half_rn(x[i]);
}

// ---------------- build W^T [n=256][k=1280], fp16 ----------------------------------
__global__ void build_wt_kernel(const float* __restrict__ basis0, const float* __restrict__ root0,
                                const float* __restrict__ basis1, const float* __restrict__ root1) {
    int idx = blockIdx.x * blockDim.x + threadIdx.x;
    if (idx >= D * KTOT) return;
    int n = idx / KTOT;
    int k = idx % KTOT;
    float v0, v1;
    if (k < NBASES * D) {
        int b = k >> 8;
        int i = k & 255;
        v0 = basis0[((size_t)b * D + i) * D + n];
        v1 = basis1[((size_t)b * D + i) * D + n];
    } else {
        v0 = root0[(size_t)(k - NBASES * D) * D + n];
        v1 = root1[(size_t)(k - NBASES * D) * D + n];
    }
    g_W0T[idx] = __float2half_rn(v0);
    g_W1T[idx] = __float2half_rn(v1);
}

// ---------------- bias staging ----------------
__global__ void copy_bias_kernel(const float* __restrict__ bias0,
                                 const float* __restrict__ bias1) {
    int i = threadIdx.x;
    if (i < D) { g_bias[0][i] = bias0[i]; g_bias[1][i] = bias1[i]; }
}

// ---------------- aggregation: S[dst, b, :] = sum_e w_b(e) feat[src], unroll x4 -----
__global__ void aggregate_kernel(int layer) {
    const uint2* __restrict__ featv = (const uint2*)(layer ? g_h1h : g_xh);
    const float4* __restrict__ ew   = layer ? g_ew1 : g_ew0;
    const int dst = blockIdx.x;
    const int t = threadIdx.x;  // 0..63, each owns 4 columns

    float4 a0 = {0.f, 0.f, 0.f, 0.f}, a1 = a0, a2 = a0, a3 = a0;
    const int beg = g_rowptr[dst];
    const int end = g_rowptr[dst + 1];
    int e = beg;

    auto accum = [&](const float4& wt, const uint2& u) {
        float2 f01 = __half22float2(*(const __half2*)&u.x);
        float2 f23 = __half22float2(*(const __half2*)&u.y);
        a0.x += wt.x * f01.x; a0.y += wt.x * f01.y; a0.z += wt.x * f23.x; a0.w += wt.x * f23.y;
        a1.x += wt.y * f01.x; a1.y += wt.y * f01.y; a1.z += wt.y * f23.x; a1.w += wt.y * f23.y;
        a2.x += wt.z * f01.x; a2.y += wt.z * f01.y; a2.z += wt.z * f23.x; a2.w += wt.z * f23.y;
        a3.x += wt.w * f01.x; a3.y += wt.w * f01.y; a3.z += wt.w * f23.x; a3.w += wt.w * f23.y;
    };

    for (; e + 4 <= end; e += 4) {
        const int s0 = __ldg(&g_csr_src[e + 0]);
        const int s1 = __ldg(&g_csr_src[e + 1]);
        const int s2 = __ldg(&g_csr_src[e + 2]);
        const int s3 = __ldg(&g_csr_src[e + 3]);
        const uint2 u0 = __ldg(&featv[(size_t)s0 * 64 + t]);
        const uint2 u1 = __ldg(&featv[(size_t)s1 * 64 + t]);
        const uint2 u2 = __ldg(&featv[(size_t)s2 * 64 + t]);
        const uint2 u3 = __ldg(&featv[(size_t)s3 * 64 + t]);
        const float4 w0 = __ldg(&ew[e + 0]);
        const float4 w1 = __ldg(&ew[e + 1]);
        const float4 w2 = __ldg(&ew[e + 2]);
        const float4 w3 = __ldg(&ew[e + 3]);
        accum(w0, u0);
        accum(w1, u1);
        accum(w2, u2);
        accum(w3, u3);
    }
    for (; e < end; ++e) {
        const int s = __ldg(&g_csr_src[e]);
        const float4 wt = __ldg(&ew[e]);
        const uint2 u = __ldg(&featv[(size_t)s * 64 + t]);
        accum(wt, u);
    }

    uint2* Sp = (uint2*)(g_Sh + (size_t)dst * 1024);
    Sp[t]       = pack4h(a0.x, a0.y, a0.z, a0.w);
    Sp[64 + t]  = pack4h(a1.x, a1.y, a1.z, a1.w);
    Sp[128 + t] = pack4h(a2.x, a2.y, a2.z, a2.w);
    Sp[192 + t] = pack4h(a3.x, a3.y, a3.z, a3.w);
}

// ---------------- fp16 tensor-core GEMM (mma.sync.m16n8k16 + ldmatrix) ------------
// C[32768,256] = A[32768,1280] @ W[1280,256] (+bias, opt relu)
// Block 128x128x32, 256 threads (8 warps: 2(M) x 4(N), warp tile 64x32).
// 3-stage cp.async pipeline, single __syncthreads per K-iteration, LDSM fragments.
#define PITCH 40                          // halfs per smem row (32 + 8 pad) = 80B
#define STAGE_HALFS (2 * 128 * PITCH)     // A[128][40] + B[128][40]
#define NSTAGE 3
#define NIT (KTOT / 32)
#define GEMM_SMEM (NSTAGE * STAGE_HALFS * 2)   // 61440 bytes

__global__ __launch_bounds__(256, 2) void gemm_fp16_kernel(float* __restrict__ out_ext, int layer) {
    extern __shared__ __half smem[];

    const __half* __restrict__ Sg = g_Sh;
    const __half* __restrict__ Rg = layer ? g_h1h : g_xh;
    const __half* __restrict__ WT = layer ? g_W1T : g_W0T;

    const int tid  = threadIdx.x;
    const int warp = tid >> 5, lane = tid & 31;
    const int g  = lane >> 2, t4 = lane & 3;
    const int wm = warp >> 2, wn = warp & 3;
    const int by = blockIdx.y * 128;
    const int bx = blockIdx.x * 128;

    const uint32_t smem_base = (uint32_t)__cvta_generic_to_shared(smem);

    // ldmatrix per-lane byte offsets (within a stage, relative to cA / cB):
    // A: lanes 0-7:(m0-7,k0) 8-15:(m8-15,k0) 16-23:(m0-7,k8) 24-31:(m8-15,k8)
    const uint32_t a_lane = (uint32_t)(((wm * 64 + (lane & 7) + ((lane >> 3) & 1) * 8) * PITCH
                                        + (lane >> 4) * 8) * 2);
    // B: lanes 0-7:(n0-7,k0) 8-15:(n0-7,k8) 16-23:(n8-15,k0) 24-31:(n8-15,k8)
    const uint32_t b_lane = (uint32_t)(((wn * 32 + (lane >> 4) * 8 + (lane & 7)) * PITCH
                                        + ((lane >> 3) & 1) * 8) * 2);

    // gmem->smem: 16B units; per operand 512 units (128 rows x 4 chunks)
    const int r16 = tid >> 1;             // 0..127 row (2 threads per row)
    const int c16 = tid & 1;              // chunk 0..1 (+2 in second pass)

    float acc[4][4][4];
#pragma unroll
    for (int i = 0; i < 4; ++i)
#pragma unroll
        for (int j = 0; j < 4; ++j)
#pragma unroll
            for (int q = 0; q < 4; ++q) acc[i][j][q] = 0.f;

    auto issue = [&](int it) {
        const int k0 = it * 32;
        const int buf = it % NSTAGE;
        const __half* Ab;
        int astr;
        if (k0 < 1024) { Ab = Sg + (size_t)by * 1024 + k0; astr = 1024; }
        else           { Ab = Rg + (size_t)by * 256 + (k0 - 1024); astr = 256; }
        const uint32_t dA = smem_base + buf * STAGE_HALFS * 2;
        const uint32_t dB = dA + 128 * PITCH * 2;
#pragma unroll
        for (int p = 0; p < 2; ++p) {
            int c = c16 + p * 2;
            cp_async16(dA + (r16 * PITCH + c * 8) * 2, Ab + (size_t)r16 * astr + c * 8);
        }
#pragma unroll
        for (int p = 0; p < 2; ++p) {
            int c = c16 + p * 2;
            cp_async16(dB + (r16 * PITCH + c * 8) * 2,
                       WT + (size_t)(bx + r16) * KTOT + k0 + c * 8);
        }
        asm volatile("cp.async.commit_group;\n" ::);
    };

    issue(0);
    issue(1);

    for (int it = 0; it < NIT; ++it) {
        if (it == NIT - 1) asm volatile("cp.async.wait_group 0;\n" ::);
        else               asm volatile("cp.async.wait_group 1;\n" ::);
        __syncthreads();
        if (it + 2 < NIT) issue(it + 2);

        const int buf = it % NSTAGE;
        const uint32_t cA = smem_base + buf * STAGE_HALFS * 2 + a_lane;
        const uint32_t cB = smem_base + buf * STAGE_HALFS * 2 + 128 * PITCH * 2 + b_lane;

#pragma unroll
        for (int kk = 0; kk < 32; kk += 16) {
            uint32_t af[4][4], bf[4][2];
#pragma unroll
            for (int mi = 0; mi < 4; ++mi)
                ldsm_x4(af[mi][0], af[mi][1], af[mi][2], af[mi][3],
                        cA + (mi * 16 * PITCH + kk) * 2);
#pragma unroll
            for (int nb = 0; nb < 2; ++nb)
                ldsm_x4(bf[2 * nb][0], bf[2 * nb][1], bf[2 * nb + 1][0], bf[2 * nb + 1][1],
                        cB + (nb * 16 * PITCH + kk) * 2);
#pragma unroll
            for (int mi = 0; mi < 4; ++mi)
#pragma unroll
                for (int ni = 0; ni < 4; ++ni)
                    mma_fp16(acc[mi][ni], af[mi], bf[ni]);
        }
    }

    // epilogue: acc[0],acc[1] -> row cols (2t4, 2t4+1); acc[2],acc[3] -> row+8
#pragma unroll
    for (int mi = 0; mi < 4; ++mi) {
        const int row = by + wm * 64 + mi * 16 + g;
#pragma unroll
        for (int ni = 0; ni < 4; ++ni) {
            const int col = bx + wn * 32 + ni * 8 + t4 * 2;
            const float b0 = g_bias[layer][col];
            const float b1 = g_bias[layer][col + 1];
            float v0 = acc[mi][ni][0] + b0, v1 = acc[mi][ni][1] + b1;
            float v2 = acc[mi][ni][2] + b0, v3 = acc[mi][ni][3] + b1;
            if (layer == 0) {
                v0 = fmaxf(v0, 0.f); v1 = fmaxf(v1, 0.f);
                v2 = fmaxf(v2, 0.f); v3 = fmaxf(v3, 0.f);
                *(__half2*)(g_h1h + (size_t)row * 256 + col)       = __floats2half2_rn(v0, v1);
                *(__half2*)(g_h1h + (size_t)(row + 8) * 256 + col) = __floats2half2_rn(v2, v3);
            } else {
                *(float2*)(out_ext + (size_t)row * 256 + col)       = make_float2(v0, v1);
                *(float2*)(out_ext + (size_t)(row + 8) * 256 + col) = make_float2(v2, v3);
            }
        }
    }
}

// ---------------- launch ----------------
extern "C" void kernel_launch(void* const* d_in, const int* in_sizes, int n_in,
                              void* d_out, int out_size) {
    const float* x      = (const float*)d_in[0];
    const int*   edges  = (const int*)d_in[3];
    const int*   rel    = (const int*)d_in[4];
    const float* basis0 = (const float*)d_in[5];
    const float* comp0  = (const float*)d_in[6];
    const float* root0  = (const float*)d_in[7];
    const float* bias0  = (const float*)d_in[8];
    const float* basis1 = (const float*)d_in[9];
    const float* comp1  = (const float*)d_in[10];
    const float* root1  = (const float*)d_in[11];
    const float* bias1  = (const float*)d_in[12];
    float* out = (float*)d_out;

    const int* src = edges;
    const int* dst = edges + NEDGES;

    cudaFuncSetAttribute(gemm_fp16_kernel,
                         cudaFuncAttributeMaxDynamicSharedMemorySize, GEMM_SMEM);

    // CSR + per-edge weights (shared by both layers)
    zero_counts_kernel<<<1408, 256>>>();
    hist_kernel<<<(NEDGES + 255) / 256, 256>>>(dst, rel);
    scan_kernel<<<1, 1024>>>();
    scatter_kernel<<<(NEDGES + 255) / 256, 256>>>(src, dst, rel, comp0, comp1);

    // fp16 operand prep
    round_x_kernel<<<(NNODES * D + 255) / 256, 256>>>(x);
    build_wt_kernel<<<(D * KTOT + 255) / 256, 256>>>(basis0, root0, basis1, root1);
    copy_bias_kernel<<<1, D>>>(bias0, bias1);

    dim3 ggrid(2, NNODES / 128);

    // Layer 0: aggregate(x) -> S; [S|x] @ W0 + bias0, ReLU -> h1
    aggregate_kernel<<<NNODES, 64>>>(0);
    gemm_fp16_kernel<<<ggrid, 256, GEMM_SMEM>>>(nullptr, 0);

    // Layer 1: aggregate(h1) -> S; [S|h1] @ W1 + bias1 -> out
    aggregate_kernel<<<NNODES, 64>>>(1);
    gemm_fp16_kernel<<<ggrid, 256, GEMM_SMEM>>>(out, 1);
}

// round 10
// speedup vs baseline: 3.4918x; 1.0238x over previous
#include <cuda_runtime.h>
#include <cuda_fp16.h>
#include <cstdint>

#define D 256
#define NNODES 32768
#define NREL 10
#define NBASES 4
#define NEDGES 524288
#define KTOT 1280          // 1024 (basis-agg part) + 256 (root part)

// ---------------- scratch (static device allocations; no cudaMalloc) ----------------
__device__ __half  g_Sh[(size_t)NNODES * 1024];  // 64 MB: aggregated basis sums (fp16)
__device__ __half  g_h1h[(size_t)NNODES * D];    // 16 MB: hidden activations (fp16)
__device__ __half  g_xh[(size_t)NNODES * D];     // 16 MB: fp16 input x
__device__ __half  g_W0T[D * KTOT];              // W^T layer0: [n=256][k=1280] (fp16)
__device__ __half  g_W1T[D * KTOT];              // W^T layer1
__device__ float   g_bias[2][D];
__device__ int     g_cnt[NREL * NNODES];
__device__ int     g_deg[NNODES];
__device__ int     g_rowptr[NNODES + 1];
__device__ int     g_cursor[NNODES];
__device__ int     g_csr_src[NEDGES];
__device__ float4  g_ew0[NEDGES];
__device__ float4  g_ew1[NEDGES];

// ---------------- helpers ----------------
__device__ __forceinline__ void cp_async16(uint32_t saddr, const void* gaddr) {
    asm volatile("cp.async.cg.shared.global [%0], [%1], 16;\n" :: "r"(saddr), "l"(gaddr));
}

__device__ __forceinline__ void mma_fp16(float* d, const uint32_t* a, const uint32_t* b) {
    asm volatile(
        "mma.sync.aligned.m16n8k16.row.col.f32.f16.f16.f32 "
        "{%0,%1,%2,%3}, {%4,%5,%6,%7}, {%8,%9}, {%0,%1,%2,%3};\n"
        : "+f"(d[0]), "+f"(d[1]), "+f"(d[2]), "+f"(d[3])
        : "r"(a[0]), "r"(a[1]), "r"(a[2]), "r"(a[3]), "r"(b[0]), "r"(b[1]));
}

__device__ __forceinline__ void ldsm_x4(uint32_t& r0, uint32_t& r1, uint32_t& r2,
                                        uint32_t& r3, uint32_t saddr) {
    asm volatile("ldmatrix.sync.aligned.m8n8.x4.shared.b16 {%0,%1,%2,%3}, [%4];"
                 : "=r"(r0), "=r"(r1), "=r"(r2), "=r"(r3) : "r"(saddr));
}

__device__ __forceinline__ void ffma2(uint64_t& acc, uint64_t a, uint64_t b) {
    asm("fma.rn.f32x2 %0, %1, %2, %0;" : "+l"(acc) : "l"(a), "l"(b));
}

__device__ __forceinline__ uint64_t packf2(float lo, float hi) {
    uint64_t v;
    asm("mov.b64 %0, {%1, %2};" : "=l"(v) : "f"(lo), "f"(hi));
    return v;
}

__device__ __forceinline__ float2 unpackf2(uint64_t v) {
    float2 o;
    asm("mov.b64 {%0, %1}, %2;" : "=f"(o.x), "=f"(o.y) : "l"(v));
    return o;
}

__device__ __forceinline__ uint2 pack4h(float x, float y, float z, float w) {
    __half2 p0 = __floats2half2_rn(x, y);
    __half2 p1 = __floats2half2_rn(z, w);
    uint2 o;
    o.x = *(uint32_t*)&p0;
    o.y = *(uint32_t*)&p1;
    return o;
}

// ---------------- zero the histogram buffers ----------------
__global__ void zero_counts_kernel() {
    int i = blockIdx.x * blockDim.x + threadIdx.x;
    int total = NNODES + NREL * NNODES;
    for (; i < total; i += gridDim.x * blockDim.x) {
        if (i < NNODES) g_deg[i] = 0;
        else            g_cnt[i - NNODES] = 0;
    }
}

// ---------------- histogram ----------------
__global__ void hist_kernel(const int* __restrict__ dst, const int* __restrict__ rel) {
    int e = blockIdx.x * blockDim.x + threadIdx.x;
    if (e >= NEDGES) return;
    int d = dst[e];
    int r = rel[e];
    atomicAdd(&g_deg[d], 1);
    atomicAdd(&g_cnt[r * NNODES + d], 1);
}

// ---------------- exclusive scan (single block) ----------------
__global__ void scan_kernel() {
    __shared__ int sums[1024];
    const int t = threadIdx.x;
    const int base = t * 32;
    int local[32];
    int s = 0;
#pragma unroll
    for (int i = 0; i < 32; ++i) { local[i] = s; s += g_deg[base + i]; }
    sums[t] = s;
    __syncthreads();
    for (int off = 1; off < 1024; off <<= 1) {
        int v = 0;
        if (t >= off) v = sums[t - off];
        __syncthreads();
        if (t >= off) sums[t] += v;
        __syncthreads();
    }
    const int chunk_off = (t == 0) ? 0 : sums[t - 1];
#pragma unroll
    for (int i = 0; i < 32; ++i) {
        int v = chunk_off + local[i];
        g_rowptr[base + i] = v;
        g_cursor[base + i] = v;
    }
    if (t == 1023) g_rowptr[NNODES] = sums[1023];
}

// ---------------- scatter: CSR order src + precomputed per-edge weights -----------
__global__ void scatter_kernel(const int* __restrict__ src, const int* __restrict__ dst,
                               const int* __restrict__ rel,
                               const float* __restrict__ comp0,
                               const float* __restrict__ comp1) {
    int e = blockIdx.x * blockDim.x + threadIdx.x;
    if (e >= NEDGES) return;
    int d = dst[e];
    int r = rel[e];
    int p = atomicAdd(&g_cursor[d], 1);
    float inv = 1.0f / (float)g_cnt[r * NNODES + d];
    g_csr_src[p] = src[e];
    g_ew0[p] = make_float4(comp0[r * 4 + 0] * inv, comp0[r * 4 + 1] * inv,
                           comp0[r * 4 + 2] * inv, comp0[r * 4 + 3] * inv);
    g_ew1[p] = make_float4(comp1[r * 4 + 0] * inv, comp1[r * 4 + 1] * inv,
                           comp1[r * 4 + 2] * inv, comp1[r * 4 + 3] * inv);
}

// ---------------- fused operand prep: x->fp16, W^T (both layers), bias -------------
__global__ void prep_kernel(const float* __restrict__ x,
                            const float* __restrict__ basis0, const float* __restrict__ root0,
                            const float* __restrict__ basis1, const float* __restrict__ root1,
                            const float* __restrict__ bias0, const float* __restrict__ bias1) {
    int i = blockIdx.x * blockDim.x + threadIdx.x;
    if (i < NNODES * D) g_xh[i] = __float2half_rn(x[i]);
    if (i < D * KTOT) {
        int n = i / KTOT;
        int k = i % KTOT;
        float v0, v1;
        if (k < NBASES * D) {
            int b = k >> 8;
            int r = k & 255;
            v0 = basis0[((size_t)b * D + r) * D + n];
            v1 = basis1[((size_t)b * D + r) * D + n];
        } else {
            v0 = root0[(size_t)(k - NBASES * D) * D + n];
            v1 = root1[(size_t)(k - NBASES * D) * D + n];
        }
        g_W0T[i] = __float2half_rn(v0);
        g_W1T[i] = __float2half_rn(v1);
    }
    if (i < D) { g_bias[0][i] = bias0[i]; g_bias[1][i] = bias1[i]; }
}

// ---------------- aggregation: S[dst, b, :] = sum_e w_b(e) feat[src] ----------------
// 256 threads per block = 4 dst nodes; packed f32x2 FFMA2 accumulation (exact).
__global__ void aggregate_kernel(int layer) {
    const uint2* __restrict__ featv = (const uint2*)(layer ? g_h1h : g_xh);
    const float4* __restrict__ ew   = layer ? g_ew1 : g_ew0;
    const int dst = blockIdx.x * 4 + (threadIdx.x >> 6);
    const int t = threadIdx.x & 63;   // each owns 4 columns

    uint64_t acc[4][2] = {};          // 4 bases x (c01, c23) packed f32x2
    const int beg = g_rowptr[dst];
    const int end = g_rowptr[dst + 1];
    int e = beg;

    auto accum = [&](const float4& wt, const uint2& u) {
        float2 f01 = __half22float2(*(const __half2*)&u.x);
        float2 f23 = __half22float2(*(const __half2*)&u.y);
        uint64_t v01 = packf2(f01.x, f01.y);
        uint64_t v23 = packf2(f23.x, f23.y);
        uint64_t w0 = packf2(wt.x, wt.x);
        uint64_t w1 = packf2(wt.y, wt.y);
        uint64_t w2 = packf2(wt.z, wt.z);
        uint64_t w3 = packf2(wt.w, wt.w);
        ffma2(acc[0][0], w0, v01); ffma2(acc[0][1], w0, v23);
        ffma2(acc[1][0], w1, v01); ffma2(acc[1][1], w1, v23);
        ffma2(acc[2][0], w2, v01); ffma2(acc[2][1], w2, v23);
        ffma2(acc[3][0], w3, v01); ffma2(acc[3][1], w3, v23);
    };

    for (; e + 4 <= end; e += 4) {
        const int s0 = __ldg(&g_csr_src[e + 0]);
        const int s1 = __ldg(&g_csr_src[e + 1]);
        const int s2 = __ldg(&g_csr_src[e + 2]);
        const int s3 = __ldg(&g_csr_src[e + 3]);
        const uint2 u0 = __ldg(&featv[(size_t)s0 * 64 + t]);
        const uint2 u1 = __ldg(&featv[(size_t)s1 * 64 + t]);
        const uint2 u2 = __ldg(&featv[(size_t)s2 * 64 + t]);
        const uint2 u3 = __ldg(&featv[(size_t)s3 * 64 + t]);
        const float4 w0 = __ldg(&ew[e + 0]);
        const float4 w1 = __ldg(&ew[e + 1]);
        const float4 w2 = __ldg(&ew[e + 2]);
        const float4 w3 = __ldg(&ew[e + 3]);
        accum(w0, u0);
        accum(w1, u1);
        accum(w2, u2);
        accum(w3, u3);
    }
    for (; e < end; ++e) {
        const int s = __ldg(&g_csr_src[e]);
        const float4 wt = __ldg(&ew[e]);
        const uint2 u = __ldg(&featv[(size_t)s * 64 + t]);
        accum(wt, u);
    }

    uint2* Sp = (uint2*)(g_Sh + (size_t)dst * 1024);
#pragma unroll
    for (int b = 0; b < 4; ++b) {
        float2 c01 = unpackf2(acc[b][0]);
        float2 c23 = unpackf2(acc[b][1]);
        Sp[b * 64 + t] = pack4h(c01.x, c01.y, c23.x, c23.y);
    }
}

// ---------------- fp16 tensor-core GEMM (mma.sync.m16n8k16 + ldmatrix) ------------
// C[32768,256] = A[32768,1280] @ W[1280,256] (+bias, opt relu)
// One CTA per 128 M-rows covers ALL N=256: 512 threads (16 warps, 2M x 8N),
// warp tile 64x32. A read ONCE per layer. 3-stage cp.async, LDSM fragments.
#define PITCH 40                               // halfs per smem row (32 + 8 pad)
#define STAGE_HALFS ((128 + 256) * PITCH)      // A[128][40] + B[256][40]
#define NSTAGE 3
#define NIT (KTOT / 32)
#define GEMM_SMEM (NSTAGE * STAGE_HALFS * 2)   // 92160 bytes

__global__ __launch_bounds__(512, 1) void gemm_fp16_kernel(float* __restrict__ out_ext, int layer) {
    extern __shared__ __half smem[];

    const __half* __restrict__ Sg = g_Sh;
    const __half* __restrict__ Rg = layer ? g_h1h : g_xh;
    const __half* __restrict__ WT = layer ? g_W1T : g_W0T;

    const int tid  = threadIdx.x;
    const int warp = tid >> 5, lane = tid & 31;
    const int g  = lane >> 2, t4 = lane & 3;
    const int wm = warp >> 3, wn = warp & 7;   // 2 x 8
    const int by = blockIdx.x * 128;

    const uint32_t smem_base = (uint32_t)__cvta_generic_to_shared(smem);

    // ldmatrix per-lane byte offsets within a stage:
    const uint32_t a_lane = (uint32_t)(((wm * 64 + (lane & 7) + ((lane >> 3) & 1) * 8) * PITCH
                                        + (lane >> 4) * 8) * 2);
    const uint32_t b_lane = (uint32_t)(((wn * 32 + (lane >> 4) * 8 + (lane & 7)) * PITCH
                                        + ((lane >> 3) & 1) * 8) * 2);

    // gmem->smem: 16B units. A: 512 units (1/thread). B: 1024 units (2/thread).
    const int r16 = tid >> 2;             // 0..127
    const int c16 = tid & 3;              // chunk 0..3

    float acc[4][4][4];
#pragma unroll
    for (int i = 0; i < 4; ++i)
#pragma unroll
        for (int j = 0; j < 4; ++j)
#pragma unroll
            for (int q = 0; q < 4; ++q) acc[i][j][q] = 0.f;

    auto issue = [&](int it) {
        const int k0 = it * 32;
        const int buf = it % NSTAGE;
        const __half* Ab;
        int astr;
        if (k0 < 1024) { Ab = Sg + (size_t)by * 1024 + k0; astr = 1024; }
        else           { Ab = Rg + (size_t)by * 256 + (k0 - 1024); astr = 256; }
        const uint32_t dA = smem_base + buf * STAGE_HALFS * 2;
        const uint32_t dB = dA + 128 * PITCH * 2;
        cp_async16(dA + (r16 * PITCH + c16 * 8) * 2, Ab + (size_t)r16 * astr + c16 * 8);
#pragma unroll
        for (int p = 0; p < 2; ++p) {
            int n = r16 + p * 128;
            cp_async16(dB + (n * PITCH + c16 * 8) * 2,
                       WT + (size_t)n * KTOT + k0 + c16 * 8);
        }
        asm volatile("cp.async.commit_group;\n" ::);
    };

    issue(0);
    issue(1);

    for (int it = 0; it < NIT; ++it) {
        if (it == NIT - 1) asm volatile("cp.async.wait_group 0;\n" ::);
        else               asm volatile("cp.async.wait_group 1;\n" ::);
        __syncthreads();
        if (it + 2 < NIT) issue(it + 2);

        const int buf = it % NSTAGE;
        const uint32_t cA = smem_base + buf * STAGE_HALFS * 2 + a_lane;
        const uint32_t cB = smem_base + buf * STAGE_HALFS * 2 + 128 * PITCH * 2 + b_lane;

#pragma unroll
        for (int kk = 0; kk < 32; kk += 16) {
            uint32_t af[4][4], bf[4][2];
#pragma unroll
            for (int mi = 0; mi < 4; ++mi)
                ldsm_x4(af[mi][0], af[mi][1], af[mi][2], af[mi][3],
                        cA + (mi * 16 * PITCH + kk) * 2);
#pragma unroll
            for (int nb = 0; nb < 2; ++nb)
                ldsm_x4(bf[2 * nb][0], bf[2 * nb][1], bf[2 * nb + 1][0], bf[2 * nb + 1][1],
                        cB + (nb * 16 * PITCH + kk) * 2);
#pragma unroll
            for (int mi = 0; mi < 4; ++mi)
#pragma unroll
                for (int ni = 0; ni < 4; ++ni)
                    mma_fp16(acc[mi][ni], af[mi], bf[ni]);
        }
    }

    // epilogue
#pragma unroll
    for (int mi = 0; mi < 4; ++mi) {
        const int row = by + wm * 64 + mi * 16 + g;
#pragma unroll
        for (int ni = 0; ni < 4; ++ni) {
            const int col = wn * 32 + ni * 8 + t4 * 2;
            const float b0 = g_bias[layer][col];
            const float b1 = g_bias[layer][col + 1];
            float v0 = acc[mi][ni][0] + b0, v1 = acc[mi][ni][1] + b1;
            float v2 = acc[mi][ni][2] + b0, v3 = acc[mi][ni][3] + b1;
            if (layer == 0) {
                v0 = fmaxf(v0, 0.f); v1 = fmaxf(v1, 0.f);
                v2 = fmaxf(v2, 0.f); v3 = fmaxf(v3, 0.f);
                *(__half2*)(g_h1h + (size_t)row * 256 + col)       = __floats2half2_rn(v0, v1);
                *(__half2*)(g_h1h + (size_t)(row + 8) * 256 + col) = __floats2half2_rn(v2, v3);
            } else {
                *(float2*)(out_ext + (size_t)row * 256 + col)       = make_float2(v0, v1);
                *(float2*)(out_ext + (size_t)(row + 8) * 256 + col) = make_float2(v2, v3);
            }
        }
    }
}

// ---------------- launch ----------------
extern "C" void kernel_launch(void* const* d_in, const int* in_sizes, int n_in,
                              void* d_out, int out_size) {
    const float* x      = (const float*)d_in[0];
    const int*   edges  = (const int*)d_in[3];
    const int*   rel    = (const int*)d_in[4];
    const float* basis0 = (const float*)d_in[5];
    const float* comp0  = (const float*)d_in[6];
    const float* root0  = (const float*)d_in[7];
    const float* bias0  = (const float*)d_in[8];
    const float* basis1 = (const float*)d_in[9];
    const float* comp1  = (const float*)d_in[10];
    const float* root1  = (const float*)d_in[11];
    const float* bias1  = (const float*)d_in[12];
    float* out = (float*)d_out;

    const int* src = edges;
    const int* dst = edges + NEDGES;

    cudaFuncSetAttribute(gemm_fp16_kernel,
                         cudaFuncAttributeMaxDynamicSharedMemorySize, GEMM_SMEM);

    // CSR + per-edge weights (shared by both layers)
    zero_counts_kernel<<<1408, 256>>>();
    hist_kernel<<<(NEDGES + 255) / 256, 256>>>(dst, rel);
    scan_kernel<<<1, 1024>>>();
    scatter_kernel<<<(NEDGES + 255) / 256, 256>>>(src, dst, rel, comp0, comp1);

    // fused fp16 operand prep
    prep_kernel<<<(NNODES * D + 255) / 256, 256>>>(x, basis0, root0, basis1, root1,
                                                   bias0, bias1);

    // Layer 0: aggregate(x) -> S; [S|x] @ W0 + bias0, ReLU -> h1
    aggregate_kernel<<<NNODES / 4, 256>>>(0);
    gemm_fp16_kernel<<<NNODES / 128, 512, GEMM_SMEM>>>(nullptr, 0);

    // Layer 1: aggregate(h1) -> S; [S|h1] @ W1 + bias1 -> out
    aggregate_kernel<<<NNODES / 4, 256>>>(1);
    gemm_fp16_kernel<<<NNODES / 128, 512, GEMM_SMEM>>>(out, 1);
}